// round 13
// baseline (speedup 1.0000x reference)
#include <cuda_runtime.h>
#include <cuda_bf16.h>
#include <stdint.h>

// ---------------- problem constants (static shapes) ----------------
#define N_OV 20000
#define N_OF 30000
#define N_SV 4000
#define N_SF 5000
#define NSAMP 50
#define N_SAMPLES 250000
// vertex grid (reverse term) — also used to sort samples
#define GRID_G 32
#define NCELLS (GRID_G * GRID_G * GRID_G)       // 32768
#define SCAN_BLOCKS 32
// barycenter grid (forward term)
#define GRID_G2 32
#define NCELLS2 (GRID_G2 * GRID_G2 * GRID_G2)   // 32768
#define SCAN_BLOCKS2 32
#define REV_BLOCKS 977                           // ceil(250000/256)
#define FWD_WARP_BLOCKS 625                      // 5000 warps
#define F1_BLOCKS (FWD_WARP_BLOCKS + REV_BLOCKS)
#define FB_BLOCKS 296                            // fallback kernel blocks
#define GEN_BLOCKS 977

// ---------------- device scratch (static, no runtime alloc) ----------------
__device__ float4    g_obp[N_OF];
__device__ float4    g_sb[N_SF];
__device__ unsigned  g_minfwd[N_SF];
__device__ float4    g_samples[N_SAMPLES];
__device__ float4    g_ssorted[N_SAMPLES];
__device__ float     g_sfp[N_SAMPLES];
__device__ float     g_dist[N_SAMPLES];
__device__ int       g_fbqueue[N_SAMPLES];
__device__ unsigned  g_fbcount;
__device__ unsigned  g_maxbits;
__device__ double    g_part[REV_BLOCKS];
__device__ unsigned  g_done;
// grid V (vertices)
__device__ unsigned  g_bbox[6];
__device__ int       g_count[NCELLS];
__device__ int       g_cursor[NCELLS];
__device__ int       g_cellstart[NCELLS + 1];
__device__ int       g_blocksum[SCAN_BLOCKS];
__device__ float4    g_sorted[N_OV];
// grid B (original barycenters)
__device__ unsigned  g_bbox2[6];
__device__ int       g_count2[NCELLS2];
__device__ int       g_cursor2[NCELLS2];
__device__ int       g_cellstart2[NCELLS2 + 1];
__device__ int       g_blocksum2[SCAN_BLOCKS2];
__device__ float4    g_sorted2[N_OF];
// grid S (samples, same geometry as grid V)
__device__ int       g_count3[NCELLS];
__device__ int       g_cursor3[NCELLS];
__device__ int       g_cellstart3[NCELLS + 1];
__device__ int       g_blocksum3[SCAN_BLOCKS];

// ---------------- ordered-float helpers ----------------
__device__ __forceinline__ unsigned f2o(float f) {
    unsigned u = __float_as_uint(f);
    return (u & 0x80000000u) ? ~u : (u | 0x80000000u);
}
__device__ __forceinline__ float o2f(unsigned u) {
    u = (u & 0x80000000u) ? (u & 0x7fffffffu) : ~u;
    return __uint_as_float(u);
}

// ---------------- threefry2x32 (JAX partitionable, 20 rounds) ----------------
__host__ __device__ constexpr uint32_t rotl32(uint32_t x, int r) {
    return (x << r) | (x >> (32 - r));
}
struct U2 { uint32_t a, b; };
__host__ __device__ constexpr U2 threefry2x32(uint32_t k0, uint32_t k1,
                                              uint32_t x0, uint32_t x1) {
    uint32_t ks0 = k0, ks1 = k1, ks2 = k0 ^ k1 ^ 0x1BD11BDAu;
    x0 += ks0; x1 += ks1;
    x0 += x1; x1 = rotl32(x1, 13); x1 ^= x0;
    x0 += x1; x1 = rotl32(x1, 15); x1 ^= x0;
    x0 += x1; x1 = rotl32(x1, 26); x1 ^= x0;
    x0 += x1; x1 = rotl32(x1,  6); x1 ^= x0;
    x0 += ks1; x1 += ks2 + 1u;
    x0 += x1; x1 = rotl32(x1, 17); x1 ^= x0;
    x0 += x1; x1 = rotl32(x1, 29); x1 ^= x0;
    x0 += x1; x1 = rotl32(x1, 16); x1 ^= x0;
    x0 += x1; x1 = rotl32(x1, 24); x1 ^= x0;
    x0 += ks2; x1 += ks0 + 2u;
    x0 += x1; x1 = rotl32(x1, 13); x1 ^= x0;
    x0 += x1; x1 = rotl32(x1, 15); x1 ^= x0;
    x0 += x1; x1 = rotl32(x1, 26); x1 ^= x0;
    x0 += x1; x1 = rotl32(x1,  6); x1 ^= x0;
    x0 += ks0; x1 += ks1 + 3u;
    x0 += x1; x1 = rotl32(x1, 17); x1 ^= x0;
    x0 += x1; x1 = rotl32(x1, 29); x1 ^= x0;
    x0 += x1; x1 = rotl32(x1, 16); x1 ^= x0;
    x0 += x1; x1 = rotl32(x1, 24); x1 ^= x0;
    x0 += ks1; x1 += ks2 + 4u;
    x0 += x1; x1 = rotl32(x1, 13); x1 ^= x0;
    x0 += x1; x1 = rotl32(x1, 15); x1 ^= x0;
    x0 += x1; x1 = rotl32(x1, 26); x1 ^= x0;
    x0 += x1; x1 = rotl32(x1,  6); x1 ^= x0;
    x0 += ks2; x1 += ks0 + 5u;
    return {x0, x1};
}
constexpr U2 RK1 = threefry2x32(0u, 42u, 0u, 0u);
constexpr U2 RK2 = threefry2x32(0u, 42u, 0u, 1u);

__device__ __forceinline__ float bits_to_uniform(uint32_t bits) {
    return __uint_as_float((bits >> 9) | 0x3f800000u) - 1.0f;
}

// ---------------- grid geometry ----------------
struct GridGeom { float x0, y0, z0, invh, h; };
__device__ __forceinline__ GridGeom load_geom(const unsigned* bbox, int G) {
    GridGeom g;
    g.x0 = o2f(bbox[0]); g.y0 = o2f(bbox[1]); g.z0 = o2f(bbox[2]);
    float ex = o2f(bbox[3]) - g.x0;
    float ey = o2f(bbox[4]) - g.y0;
    float ez = o2f(bbox[5]) - g.z0;
    float e = fmaxf(fmaxf(ex, ey), fmaxf(ez, 1e-20f));
    g.h = e / (float)G;
    g.invh = (float)G / e;
    return g;
}
__device__ __forceinline__ int cell_coord(float v, float v0, float invh, int G) {
    int c = (int)((v - v0) * invh);
    return min(max(c, 0), G - 1);
}

// ---------------- warp-cooperative exact shell search (returns d2) ---------
// All 32 lanes participate; lanes stride points in each row segment.
template <int G>
__device__ __forceinline__ float warp_shell_nn(float qx, float qy, float qz, float qw,
                                               const GridGeom g,
                                               const int* __restrict__ cellstart,
                                               const float4* __restrict__ sorted,
                                               int lane) {
    float m2x = -2.0f * qx, m2y = -2.0f * qy, m2z = -2.0f * qz;
    int cx = cell_coord(qx, g.x0, g.invh, G);
    int cy = cell_coord(qy, g.y0, g.invh, G);
    int cz = cell_coord(qz, g.z0, g.invh, G);

    float best = 3.0e38f;
    for (int R = 0; R <= G; R++) {
        float bmin = best;
#pragma unroll
        for (int o = 16; o > 0; o >>= 1)
            bmin = fminf(bmin, __shfl_xor_sync(0xffffffffu, bmin, o));
        if (R > 0) {
            float lb = (float)(R - 1) * g.h;
            if (bmin + qw <= lb * lb) { best = bmin; break; }
        }
        best = bmin;
        int zlo = max(cz - R, 0), zhi = min(cz + R, G - 1);
        int ylo = max(cy - R, 0), yhi = min(cy + R, G - 1);
        int xlo = max(cx - R, 0), xhi = min(cx + R, G - 1);
        for (int z = zlo; z <= zhi; z++) {
            bool ze = (z == cz - R) || (z == cz + R);
            for (int y = ylo; y <= yhi; y++) {
                bool edge = ze || (y == cy - R) || (y == cy + R);
                int rowbase = (z * G + y) * G;
                if (edge) {
                    int p0 = __ldg(&cellstart[rowbase + xlo]);
                    int p1 = __ldg(&cellstart[rowbase + xhi + 1]);
                    for (int p = p0 + lane; p < p1; p += 32) {
                        float4 v = sorted[p];
                        float t = fmaf(v.x, m2x, fmaf(v.y, m2y, fmaf(v.z, m2z, v.w)));
                        best = fminf(best, t);
                    }
                } else {
                    int xa = cx - R, xb = cx + R;
                    if (xa >= 0) {
                        int c0 = rowbase + xa;
                        int p0 = __ldg(&cellstart[c0]), p1 = __ldg(&cellstart[c0 + 1]);
                        for (int p = p0 + lane; p < p1; p += 32) {
                            float4 v = sorted[p];
                            float t = fmaf(v.x, m2x, fmaf(v.y, m2y, fmaf(v.z, m2z, v.w)));
                            best = fminf(best, t);
                        }
                    }
                    if (xb <= G - 1) {
                        int c0 = rowbase + xb;
                        int p0 = __ldg(&cellstart[c0]), p1 = __ldg(&cellstart[c0 + 1]);
                        for (int p = p0 + lane; p < p1; p += 32) {
                            float4 v = sorted[p];
                            float t = fmaf(v.x, m2x, fmaf(v.y, m2y, fmaf(v.z, m2z, v.w)));
                            best = fminf(best, t);
                        }
                    }
                }
            }
        }
        if (zlo == 0 && ylo == 0 && xlo == 0 &&
            zhi == G - 1 && yhi == G - 1 && xhi == G - 1) {
            float bm = best;
#pragma unroll
            for (int o = 16; o > 0; o >>= 1)
                bm = fminf(bm, __shfl_xor_sync(0xffffffffu, bm, o));
            best = bm;
            break;
        }
    }
    return fmaxf(best + qw, 0.0f);
}

// ---------------- kernel A: fused init + prep ----------------
__global__ void init_prep_kernel(const float* __restrict__ ov,
                                 const int*   __restrict__ of,
                                 const float* __restrict__ sv,
                                 const int*   __restrict__ sf) {
    int i = blockIdx.x * 256 + threadIdx.x;
    if (i < NCELLS)  { g_count[i] = 0;  g_cursor[i] = 0;
                       g_count3[i] = 0; g_cursor3[i] = 0; }
    if (i < NCELLS2) { g_count2[i] = 0; g_cursor2[i] = 0; }
    if (i == 0) {
        g_maxbits = 0u;
        g_done = 0u;
        g_fbcount = 0u;
        for (int k = 0; k < 3; k++) { g_bbox[k] = 0xFFFFFFFFu;  g_bbox[k + 3] = 0u; }
        for (int k = 0; k < 3; k++) { g_bbox2[k] = 0xFFFFFFFFu; g_bbox2[k + 3] = 0u; }
    }

    // bbox of original vertices
    {
        float mnx =  3.0e38f, mxx = -3.0e38f;
        float mny =  3.0e38f, mxy = -3.0e38f;
        float mnz =  3.0e38f, mxz = -3.0e38f;
        if (i < N_OV) {
            mnx = mxx = ov[3 * i];
            mny = mxy = ov[3 * i + 1];
            mnz = mxz = ov[3 * i + 2];
        }
#pragma unroll
        for (int o = 16; o > 0; o >>= 1) {
            mnx = fminf(mnx, __shfl_xor_sync(0xffffffffu, mnx, o));
            mny = fminf(mny, __shfl_xor_sync(0xffffffffu, mny, o));
            mnz = fminf(mnz, __shfl_xor_sync(0xffffffffu, mnz, o));
            mxx = fmaxf(mxx, __shfl_xor_sync(0xffffffffu, mxx, o));
            mxy = fmaxf(mxy, __shfl_xor_sync(0xffffffffu, mxy, o));
            mxz = fmaxf(mxz, __shfl_xor_sync(0xffffffffu, mxz, o));
        }
        if ((threadIdx.x & 31) == 0 && (blockIdx.x * 256 + (threadIdx.x & ~31)) < N_OV) {
            atomicMin(&g_bbox[0], f2o(mnx));
            atomicMin(&g_bbox[1], f2o(mny));
            atomicMin(&g_bbox[2], f2o(mnz));
            atomicMax(&g_bbox[3], f2o(mxx));
            atomicMax(&g_bbox[4], f2o(mxy));
            atomicMax(&g_bbox[5], f2o(mxz));
        }
    }
    // original barycenters + their bbox
    {
        float bx, by, bz;
        float mnx =  3.0e38f, mxx = -3.0e38f;
        float mny =  3.0e38f, mxy = -3.0e38f;
        float mnz =  3.0e38f, mxz = -3.0e38f;
        if (i < N_OF) {
            int f0 = of[3 * i], f1 = of[3 * i + 1], f2 = of[3 * i + 2];
            bx = (ov[3 * f0] + ov[3 * f1] + ov[3 * f2]) / 3.0f;
            by = (ov[3 * f0 + 1] + ov[3 * f1 + 1] + ov[3 * f2 + 1]) / 3.0f;
            bz = (ov[3 * f0 + 2] + ov[3 * f1 + 2] + ov[3 * f2 + 2]) / 3.0f;
            g_obp[i] = make_float4(bx, by, bz, bx * bx + by * by + bz * bz);
            mnx = mxx = bx; mny = mxy = by; mnz = mxz = bz;
        }
#pragma unroll
        for (int o = 16; o > 0; o >>= 1) {
            mnx = fminf(mnx, __shfl_xor_sync(0xffffffffu, mnx, o));
            mny = fminf(mny, __shfl_xor_sync(0xffffffffu, mny, o));
            mnz = fminf(mnz, __shfl_xor_sync(0xffffffffu, mnz, o));
            mxx = fmaxf(mxx, __shfl_xor_sync(0xffffffffu, mxx, o));
            mxy = fmaxf(mxy, __shfl_xor_sync(0xffffffffu, mxy, o));
            mxz = fmaxf(mxz, __shfl_xor_sync(0xffffffffu, mxz, o));
        }
        if ((threadIdx.x & 31) == 0 && (blockIdx.x * 256 + (threadIdx.x & ~31)) < N_OF) {
            atomicMin(&g_bbox2[0], f2o(mnx));
            atomicMin(&g_bbox2[1], f2o(mny));
            atomicMin(&g_bbox2[2], f2o(mnz));
            atomicMax(&g_bbox2[3], f2o(mxx));
            atomicMax(&g_bbox2[4], f2o(mxy));
            atomicMax(&g_bbox2[5], f2o(mxz));
        }
    }
    if (i < N_SF) {
        int f0 = sf[3 * i], f1 = sf[3 * i + 1], f2 = sf[3 * i + 2];
        float bx = (sv[3 * f0] + sv[3 * f1] + sv[3 * f2]) / 3.0f;
        float by = (sv[3 * f0 + 1] + sv[3 * f1 + 1] + sv[3 * f2 + 1]) / 3.0f;
        float bz = (sv[3 * f0 + 2] + sv[3 * f1 + 2] + sv[3 * f2 + 2]) / 3.0f;
        g_sb[i] = make_float4(bx, by, bz, bx * bx + by * by + bz * bz);
    }
}

// ---------------- kernel B: sample gen + ALL cell counts ----------------
__global__ void gen_count_kernel(const float* __restrict__ ov,
                                 const float* __restrict__ sv,
                                 const int*   __restrict__ sf) {
    int j = blockIdx.x * 256 + threadIdx.x;

    if (j < N_SAMPLES) {
        U2 ua = threefry2x32(RK1.a, RK1.b, 0u, (uint32_t)j);
        U2 ub = threefry2x32(RK2.a, RK2.b, 0u, (uint32_t)j);

        float u1 = bits_to_uniform(ua.a ^ ua.b);
        float r2 = bits_to_uniform(ub.a ^ ub.b);
        float sq = sqrtf(u1);
        float a = 1.0f - sq;
        float b = sq * (1.0f - r2);
        float c = sq * r2;
        int f = j / NSAMP;
        int i0 = sf[3 * f], i1 = sf[3 * f + 1], i2 = sf[3 * f + 2];
        float x = a * sv[3 * i0]     + b * sv[3 * i1]     + c * sv[3 * i2];
        float y = a * sv[3 * i0 + 1] + b * sv[3 * i1 + 1] + c * sv[3 * i2 + 1];
        float z = a * sv[3 * i0 + 2] + b * sv[3 * i1 + 2] + c * sv[3 * i2 + 2];
        g_samples[j] = make_float4(x, y, z, x * x + y * y + z * z);

        GridGeom g = load_geom(g_bbox, GRID_G);
        int cx = cell_coord(x, g.x0, g.invh, GRID_G);
        int cy = cell_coord(y, g.y0, g.invh, GRID_G);
        int cz = cell_coord(z, g.z0, g.invh, GRID_G);
        atomicAdd(&g_count3[(cz * GRID_G + cy) * GRID_G + cx], 1);
    }
    if (j < N_OV) {
        GridGeom g = load_geom(g_bbox, GRID_G);
        int cx = cell_coord(ov[3 * j],     g.x0, g.invh, GRID_G);
        int cy = cell_coord(ov[3 * j + 1], g.y0, g.invh, GRID_G);
        int cz = cell_coord(ov[3 * j + 2], g.z0, g.invh, GRID_G);
        atomicAdd(&g_count[(cz * GRID_G + cy) * GRID_G + cx], 1);
    }
    if (j < N_OF) {
        GridGeom g = load_geom(g_bbox2, GRID_G2);
        float4 b = g_obp[j];
        int cx = cell_coord(b.x, g.x0, g.invh, GRID_G2);
        int cy = cell_coord(b.y, g.y0, g.invh, GRID_G2);
        int cz = cell_coord(b.z, g.z0, g.invh, GRID_G2);
        atomicAdd(&g_count2[(cz * GRID_G2 + cy) * GRID_G2 + cx], 1);
    }
}

// ---------------- scan helpers ----------------
__device__ __forceinline__ void block_scan_1024(const int* __restrict__ cnt_arr,
                                                int* __restrict__ start_arr,
                                                int* __restrict__ bsum_arr,
                                                int seg_block) {
    __shared__ int sd[1024];
    int tid = threadIdx.x;
    int cell = seg_block * 1024 + tid;
    int cnt = cnt_arr[cell];
    sd[tid] = cnt;
    __syncthreads();
#pragma unroll
    for (int off = 1; off < 1024; off <<= 1) {
        int v = (tid >= off) ? sd[tid - off] : 0;
        __syncthreads();
        sd[tid] += v;
        __syncthreads();
    }
    start_arr[cell] = sd[tid] - cnt;
    if (tid == 1023) bsum_arr[seg_block] = sd[1023];
}

// ---------------- kernel C: block-level scans (3 grids, 96 blocks) ---------
__global__ void __launch_bounds__(1024) scan1_kernel() {
    int b = blockIdx.x;
    if (b < SCAN_BLOCKS) {
        block_scan_1024(g_count, g_cellstart, g_blocksum, b);
    } else if (b < SCAN_BLOCKS + SCAN_BLOCKS2) {
        block_scan_1024(g_count2, g_cellstart2, g_blocksum2, b - SCAN_BLOCKS);
    } else {
        block_scan_1024(g_count3, g_cellstart3, g_blocksum3, b - SCAN_BLOCKS - SCAN_BLOCKS2);
    }
}

// ---------------- kernel D: add offsets (inline top scan, 96 blocks) -------
__global__ void __launch_bounds__(1024) scan3_kernel() {
    int b = blockIdx.x;
    int tid = threadIdx.x;
    const int* bsum;
    int* cs;
    int bb;
    int total_idx;
    if (b < SCAN_BLOCKS)                      { bsum = g_blocksum;  cs = g_cellstart;  bb = b;                          total_idx = NCELLS; }
    else if (b < SCAN_BLOCKS + SCAN_BLOCKS2)  { bsum = g_blocksum2; cs = g_cellstart2; bb = b - SCAN_BLOCKS;            total_idx = NCELLS2; }
    else                                      { bsum = g_blocksum3; cs = g_cellstart3; bb = b - SCAN_BLOCKS - SCAN_BLOCKS2; total_idx = NCELLS; }

    __shared__ int s_off, s_tot;
    if (tid < 32) {
        int v = bsum[tid];
        int s = v;
#pragma unroll
        for (int off = 1; off < 32; off <<= 1) {
            int t = __shfl_up_sync(0xffffffffu, s, off);
            if (tid >= off) s += t;
        }
        if (tid == (unsigned)bb) s_off = s - v;
        if (tid == 31) s_tot = s;
    }
    __syncthreads();
    cs[bb * 1024 + tid] += s_off;
    if (bb == 31 && tid == 0) cs[total_idx] = s_tot;
}

// ---------------- kernel E: scatter (vertices, barycenters, samples) -------
__global__ void scatter_kernel(const float* __restrict__ ov,
                               const float* __restrict__ fp) {
    int i = blockIdx.x * 256 + threadIdx.x;
    if (i < N_OV) {
        GridGeom g = load_geom(g_bbox, GRID_G);
        float x = ov[3 * i], y = ov[3 * i + 1], z = ov[3 * i + 2];
        int cx = cell_coord(x, g.x0, g.invh, GRID_G);
        int cy = cell_coord(y, g.y0, g.invh, GRID_G);
        int cz = cell_coord(z, g.z0, g.invh, GRID_G);
        int c = (cz * GRID_G + cy) * GRID_G + cx;
        int pos = g_cellstart[c] + atomicAdd(&g_cursor[c], 1);
        g_sorted[pos] = make_float4(x, y, z, x * x + y * y + z * z);
    }
    if (i < N_OF) {
        GridGeom g = load_geom(g_bbox2, GRID_G2);
        float4 b = g_obp[i];
        int cx = cell_coord(b.x, g.x0, g.invh, GRID_G2);
        int cy = cell_coord(b.y, g.y0, g.invh, GRID_G2);
        int cz = cell_coord(b.z, g.z0, g.invh, GRID_G2);
        int c = (cz * GRID_G2 + cy) * GRID_G2 + cx;
        int pos = g_cellstart2[c] + atomicAdd(&g_cursor2[c], 1);
        g_sorted2[pos] = b;
    }
    if (i < N_SAMPLES) {
        GridGeom g = load_geom(g_bbox, GRID_G);
        float4 s = g_samples[i];
        int cx = cell_coord(s.x, g.x0, g.invh, GRID_G);
        int cy = cell_coord(s.y, g.y0, g.invh, GRID_G);
        int cz = cell_coord(s.z, g.z0, g.invh, GRID_G);
        int c = (cz * GRID_G + cy) * GRID_G + cx;
        int pos = g_cellstart3[c] + atomicAdd(&g_cursor3[c], 1);
        g_ssorted[pos] = s;
        g_sfp[pos] = fp[i / NSAMP];
    }
}

// ---------------- kernel F1: fused forward + reverse fast-box ---------------
__global__ void __launch_bounds__(256) f1_kernel() {
    int b = blockIdx.x;
    int tid = threadIdx.x;

    if (b < FWD_WARP_BLOCKS) {
        // forward: one warp per simplified barycenter (full warp shell search)
        int warp = (b * 256 + tid) >> 5;
        int lane = tid & 31;
        if (warp >= N_SF) return;
        GridGeom g = load_geom(g_bbox2, GRID_G2);
        float4 Q = g_sb[warp];
        float d2 = warp_shell_nn<GRID_G2>(Q.x, Q.y, Q.z, Q.w, g,
                                          g_cellstart2, g_sorted2, lane);
        if (lane == 0) g_minfwd[warp] = __float_as_uint(d2);
        return;
    }

    // reverse fast path: one thread per cell-sorted sample, 2x2x2 certified box
    int j = (b - FWD_WARP_BLOCKS) * 256 + tid;
    if (j >= N_SAMPLES) return;

    GridGeom g = load_geom(g_bbox, GRID_G);
    const int G = GRID_G;
    float4 s = g_ssorted[j];
    float m2x = -2.0f * s.x, m2y = -2.0f * s.y, m2z = -2.0f * s.z;
    float fx = (s.x - g.x0) * g.invh;
    float fy = (s.y - g.y0) * g.invh;
    float fz = (s.z - g.z0) * g.invh;
    int cx = min(max((int)fx, 0), G - 1);
    int cy = min(max((int)fy, 0), G - 1);
    int cz = min(max((int)fz, 0), G - 1);

    int bx = ((fx - (float)cx) >= 0.5f) ? cx : cx - 1;
    int by = ((fy - (float)cy) >= 0.5f) ? cy : cy - 1;
    int bz = ((fz - (float)cz) >= 0.5f) ? cz : cz - 1;
    int xlo = max(bx, 0), xhi = min(bx + 1, G - 1);
    int ylo = max(by, 0), yhi = min(by + 1, G - 1);
    int zlo = max(bz, 0), zhi = min(bz + 1, G - 1);

    float cov = 3.0e38f;
    if (xlo > 0)     cov = fminf(cov, s.x - (g.x0 + (float)xlo * g.h));
    if (xhi < G - 1) cov = fminf(cov, (g.x0 + (float)(xhi + 1) * g.h) - s.x);
    if (ylo > 0)     cov = fminf(cov, s.y - (g.y0 + (float)ylo * g.h));
    if (yhi < G - 1) cov = fminf(cov, (g.y0 + (float)(yhi + 1) * g.h) - s.y);
    if (zlo > 0)     cov = fminf(cov, s.z - (g.z0 + (float)zlo * g.h));
    if (zhi < G - 1) cov = fminf(cov, (g.z0 + (float)(zhi + 1) * g.h) - s.z);
    cov = fmaxf(cov, 0.0f) * 0.99999f;

    float best = 3.0e38f;
    for (int z = zlo; z <= zhi; z++) {
        for (int y = ylo; y <= yhi; y++) {
            int rowbase = (z * G + y) * G;
            int p0 = __ldg(&g_cellstart[rowbase + xlo]);
            int p1 = __ldg(&g_cellstart[rowbase + xhi + 1]);
            for (int p = p0; p < p1; p++) {
                float4 v = g_sorted[p];
                float t = fmaf(v.x, m2x, fmaf(v.y, m2y, fmaf(v.z, m2z, v.w)));
                best = fminf(best, t);
            }
        }
    }
    float d2 = fmaxf(best + s.w, 0.0f);
    g_dist[j] = sqrtf(d2);   // provisional if fallback (overwritten by F2)
    if (d2 > cov * cov) {
        unsigned q = atomicAdd(&g_fbcount, 1u);
        g_fbqueue[q] = j;
    }
}

// ---------------- kernel F2: fallback, one WARP per hard sample ------------
__global__ void __launch_bounds__(256) f2_kernel() {
    int gwarp = (blockIdx.x * 256 + threadIdx.x) >> 5;
    int lane = threadIdx.x & 31;
    int nwarps = FB_BLOCKS * 8;
    unsigned count = g_fbcount;

    GridGeom g = load_geom(g_bbox, GRID_G);
    for (unsigned k = gwarp; k < count; k += nwarps) {
        int j = g_fbqueue[k];
        float4 s = g_ssorted[j];
        float d2 = warp_shell_nn<GRID_G>(s.x, s.y, s.z, s.w, g,
                                         g_cellstart, g_sorted, lane);
        if (lane == 0) g_dist[j] = sqrtf(d2);
    }
}

// ---------------- kernel F3: deterministic reduction + final ---------------
__global__ void __launch_bounds__(256) f3_kernel(const float* __restrict__ fp,
                                                 float* __restrict__ out) {
    int b = blockIdx.x;
    int tid = threadIdx.x;

    // partial sums over fixed chunk
    double contrib = 0.0;
    float dmax = 0.0f;
    int j = b * 256 + tid;
    if (j < N_SAMPLES) {
        float d = g_dist[j];
        contrib = (double)(g_sfp[j] * d);
        dmax = d;
    }
    __shared__ double rsum[256];
    __shared__ float rmax[256];
    rsum[tid] = contrib;
    rmax[tid] = dmax;
    __syncthreads();
#pragma unroll
    for (int o = 128; o > 0; o >>= 1) {
        if (tid < o) {
            rsum[tid] += rsum[tid + o];
            rmax[tid] = fmaxf(rmax[tid], rmax[tid + o]);
        }
        __syncthreads();
    }
    if (tid == 0) {
        g_part[b] = rsum[0];
        atomicMax(&g_maxbits, __float_as_uint(rmax[0]));
    }

    __syncthreads();
    __threadfence();
    __shared__ unsigned s_rank;
    if (tid == 0) s_rank = atomicAdd(&g_done, 1u);
    __syncthreads();
    if (s_rank != REV_BLOCKS - 1) return;

    __shared__ double red[256];
    double fwd = 0.0, pen = 0.0, rev = 0.0;
    for (int i = tid; i < N_SF; i += 256) {
        float p = fp[i];
        float d2 = __uint_as_float(g_minfwd[i]);
        fwd += (double)(p * sqrtf(d2));
        pen += (double)(1.0f - p);
    }
    for (int k = tid; k < REV_BLOCKS; k += 256) rev += g_part[k];

    double totF, totP, totR;
    red[tid] = fwd; __syncthreads();
#pragma unroll
    for (int o = 128; o > 0; o >>= 1) { if (tid < o) red[tid] += red[tid + o]; __syncthreads(); }
    totF = red[0]; __syncthreads();
    red[tid] = pen; __syncthreads();
#pragma unroll
    for (int o = 128; o > 0; o >>= 1) { if (tid < o) red[tid] += red[tid + o]; __syncthreads(); }
    totP = red[0]; __syncthreads();
    red[tid] = rev; __syncthreads();
#pragma unroll
    for (int o = 128; o > 0; o >>= 1) { if (tid < o) red[tid] += red[tid + o]; __syncthreads(); }
    totR = red[0];

    if (tid == 0) {
        double maxd = (double)__uint_as_float(g_maxbits);
        double result = totF + 1e-4 * totP + totR / (maxd + 1e-8) * 0.1;
        out[0] = (float)result;
    }
}

// ---------------- launch ----------------
extern "C" void kernel_launch(void* const* d_in, const int* in_sizes, int n_in,
                              void* d_out, int out_size) {
    const float* ov = (const float*)d_in[0];
    const int*   of = (const int*)  d_in[1];
    const float* sv = (const float*)d_in[2];
    const int*   sf = (const int*)  d_in[3];
    const float* fp = (const float*)d_in[4];
    float* out = (float*)d_out;

    init_prep_kernel<<<(NCELLS + 255) / 256, 256>>>(ov, of, sv, sf);
    gen_count_kernel<<<GEN_BLOCKS, 256>>>(ov, sv, sf);
    scan1_kernel<<<3 * SCAN_BLOCKS, 1024>>>();
    scan3_kernel<<<3 * SCAN_BLOCKS, 1024>>>();
    scatter_kernel<<<GEN_BLOCKS, 256>>>(ov, fp);
    f1_kernel<<<F1_BLOCKS, 256>>>();
    f2_kernel<<<FB_BLOCKS, 256>>>();
    f3_kernel<<<REV_BLOCKS, 256>>>(fp, out);
}

// round 14
// speedup vs baseline: 1.1477x; 1.1477x over previous
#include <cuda_runtime.h>
#include <cuda_bf16.h>
#include <stdint.h>

// ---------------- problem constants (static shapes) ----------------
#define N_OV 20000
#define N_OF 30000
#define N_SV 4000
#define N_SF 5000
#define NSAMP 50
#define N_SAMPLES 250000
// vertex grid (reverse term) — also used to sort samples
#define GRID_G 32
#define NCELLS (GRID_G * GRID_G * GRID_G)       // 32768
#define SCAN_BLOCKS 32
// barycenter grid (forward term)
#define GRID_G2 32
#define NCELLS2 (GRID_G2 * GRID_G2 * GRID_G2)   // 32768
#define SCAN_BLOCKS2 32
#define REV_BLOCKS 977                           // ceil(250000/256)
#define FWD_WARP_BLOCKS 625                      // 5000 warps
#define FUSED_BLOCKS (FWD_WARP_BLOCKS + REV_BLOCKS)
#define GEN_BLOCKS 977
#define TOTAL_SCAN_BLOCKS 96

// ---------------- device scratch (static, no runtime alloc) ----------------
__device__ float4    g_obp[N_OF];
__device__ float4    g_sb[N_SF];
__device__ unsigned  g_minfwd[N_SF];
__device__ float4    g_samples[N_SAMPLES];
__device__ float4    g_ssorted[N_SAMPLES];
__device__ float     g_sfp[N_SAMPLES];
__device__ unsigned  g_maxbits;
__device__ double    g_part[REV_BLOCKS];
__device__ unsigned  g_done;
__device__ int       g_scan_arrive;
// grid V (vertices)
__device__ unsigned  g_bbox[6];
__device__ int       g_count[NCELLS];
__device__ int       g_cursor[NCELLS];
__device__ int       g_cellstart[NCELLS + 1];
__device__ int       g_blocksum[SCAN_BLOCKS];
__device__ float4    g_sorted[N_OV];
// grid B (original barycenters)
__device__ unsigned  g_bbox2[6];
__device__ int       g_count2[NCELLS2];
__device__ int       g_cursor2[NCELLS2];
__device__ int       g_cellstart2[NCELLS2 + 1];
__device__ int       g_blocksum2[SCAN_BLOCKS2];
__device__ float4    g_sorted2[N_OF];
// grid S (samples, same geometry as grid V)
__device__ int       g_count3[NCELLS];
__device__ int       g_cursor3[NCELLS];
__device__ int       g_cellstart3[NCELLS + 1];
__device__ int       g_blocksum3[SCAN_BLOCKS];

// ---------------- ordered-float helpers ----------------
__device__ __forceinline__ unsigned f2o(float f) {
    unsigned u = __float_as_uint(f);
    return (u & 0x80000000u) ? ~u : (u | 0x80000000u);
}
__device__ __forceinline__ float o2f(unsigned u) {
    u = (u & 0x80000000u) ? (u & 0x7fffffffu) : ~u;
    return __uint_as_float(u);
}

// ---------------- threefry2x32 (JAX partitionable, 20 rounds) ----------------
__host__ __device__ constexpr uint32_t rotl32(uint32_t x, int r) {
    return (x << r) | (x >> (32 - r));
}
struct U2 { uint32_t a, b; };
__host__ __device__ constexpr U2 threefry2x32(uint32_t k0, uint32_t k1,
                                              uint32_t x0, uint32_t x1) {
    uint32_t ks0 = k0, ks1 = k1, ks2 = k0 ^ k1 ^ 0x1BD11BDAu;
    x0 += ks0; x1 += ks1;
    x0 += x1; x1 = rotl32(x1, 13); x1 ^= x0;
    x0 += x1; x1 = rotl32(x1, 15); x1 ^= x0;
    x0 += x1; x1 = rotl32(x1, 26); x1 ^= x0;
    x0 += x1; x1 = rotl32(x1,  6); x1 ^= x0;
    x0 += ks1; x1 += ks2 + 1u;
    x0 += x1; x1 = rotl32(x1, 17); x1 ^= x0;
    x0 += x1; x1 = rotl32(x1, 29); x1 ^= x0;
    x0 += x1; x1 = rotl32(x1, 16); x1 ^= x0;
    x0 += x1; x1 = rotl32(x1, 24); x1 ^= x0;
    x0 += ks2; x1 += ks0 + 2u;
    x0 += x1; x1 = rotl32(x1, 13); x1 ^= x0;
    x0 += x1; x1 = rotl32(x1, 15); x1 ^= x0;
    x0 += x1; x1 = rotl32(x1, 26); x1 ^= x0;
    x0 += x1; x1 = rotl32(x1,  6); x1 ^= x0;
    x0 += ks0; x1 += ks1 + 3u;
    x0 += x1; x1 = rotl32(x1, 17); x1 ^= x0;
    x0 += x1; x1 = rotl32(x1, 29); x1 ^= x0;
    x0 += x1; x1 = rotl32(x1, 16); x1 ^= x0;
    x0 += x1; x1 = rotl32(x1, 24); x1 ^= x0;
    x0 += ks1; x1 += ks2 + 4u;
    x0 += x1; x1 = rotl32(x1, 13); x1 ^= x0;
    x0 += x1; x1 = rotl32(x1, 15); x1 ^= x0;
    x0 += x1; x1 = rotl32(x1, 26); x1 ^= x0;
    x0 += x1; x1 = rotl32(x1,  6); x1 ^= x0;
    x0 += ks2; x1 += ks0 + 5u;
    return {x0, x1};
}
constexpr U2 RK1 = threefry2x32(0u, 42u, 0u, 0u);
constexpr U2 RK2 = threefry2x32(0u, 42u, 0u, 1u);

__device__ __forceinline__ float bits_to_uniform(uint32_t bits) {
    return __uint_as_float((bits >> 9) | 0x3f800000u) - 1.0f;
}

// ---------------- grid geometry ----------------
struct GridGeom { float x0, y0, z0, invh, h; };
__device__ __forceinline__ GridGeom load_geom(const unsigned* bbox, int G) {
    GridGeom g;
    g.x0 = o2f(bbox[0]); g.y0 = o2f(bbox[1]); g.z0 = o2f(bbox[2]);
    float ex = o2f(bbox[3]) - g.x0;
    float ey = o2f(bbox[4]) - g.y0;
    float ez = o2f(bbox[5]) - g.z0;
    float e = fmaxf(fmaxf(ex, ey), fmaxf(ez, 1e-20f));
    g.h = e / (float)G;
    g.invh = (float)G / e;
    return g;
}
__device__ __forceinline__ int cell_coord(float v, float v0, float invh, int G) {
    int c = (int)((v - v0) * invh);
    return min(max(c, 0), G - 1);
}

// ---------------- exact 1-NN: unrolled 3^3 box (MLP) + shells R>=2 ---------
template <int G>
__device__ __forceinline__ float shell_nn(float qx, float qy, float qz, float qw,
                                          const GridGeom g,
                                          const int* __restrict__ cellstart,
                                          const float4* __restrict__ sorted) {
    float m2x = -2.0f * qx, m2y = -2.0f * qy, m2z = -2.0f * qz;
    int cx = cell_coord(qx, g.x0, g.invh, G);
    int cy = cell_coord(qy, g.y0, g.invh, G);
    int cz = cell_coord(qz, g.z0, g.invh, G);

    // ---- unrolled 3x3x3 box: 9 row segments, all bounds loaded up front ----
    int xlo = max(cx - 1, 0), xhi = min(cx + 1, G - 1);
    int ys[3], zs[3];
    ys[0] = max(cy - 1, 0); ys[1] = cy; ys[2] = min(cy + 1, G - 1);
    zs[0] = max(cz - 1, 0); zs[1] = cz; zs[2] = min(cz + 1, G - 1);
    // duplicated rows (when clamped) only re-min the same values — exact.
    int p0[9], p1[9];
#pragma unroll
    for (int a = 0; a < 3; a++) {
#pragma unroll
        for (int q = 0; q < 3; q++) {
            int rowbase = (zs[a] * G + ys[q]) * G;
            p0[a * 3 + q] = __ldg(&cellstart[rowbase + xlo]);
            p1[a * 3 + q] = __ldg(&cellstart[rowbase + xhi + 1]);
        }
    }
    float best = 3.0e38f;
#pragma unroll
    for (int r = 0; r < 9; r++) {
        for (int p = p0[r]; p < p1[r]; p++) {
            float4 v = sorted[p];
            float t = fmaf(v.x, m2x, fmaf(v.y, m2y, fmaf(v.z, m2z, v.w)));
            best = fminf(best, t);
        }
    }

    // ---- expanding shells R >= 2 (box == R<=1 complete) ----
    for (int R = 2; R <= G; R++) {
        float lb = (float)(R - 1) * g.h;
        if (best + qw <= lb * lb) break;
        int szlo = max(cz - R, 0), szhi = min(cz + R, G - 1);
        int sylo = max(cy - R, 0), syhi = min(cy + R, G - 1);
        int sxlo = max(cx - R, 0), sxhi = min(cx + R, G - 1);
        for (int z = szlo; z <= szhi; z++) {
            bool ze = (z == cz - R) || (z == cz + R);
            for (int y = sylo; y <= syhi; y++) {
                bool edge = ze || (y == cy - R) || (y == cy + R);
                int rowbase = (z * G + y) * G;
                if (edge) {
                    int q0 = __ldg(&cellstart[rowbase + sxlo]);
                    int q1 = __ldg(&cellstart[rowbase + sxhi + 1]);
                    for (int p = q0; p < q1; p++) {
                        float4 v = sorted[p];
                        float t = fmaf(v.x, m2x, fmaf(v.y, m2y, fmaf(v.z, m2z, v.w)));
                        best = fminf(best, t);
                    }
                } else {
                    int xa = cx - R, xb = cx + R;
                    if (xa >= 0) {
                        int c0 = rowbase + xa;
                        int q0 = __ldg(&cellstart[c0]), q1 = __ldg(&cellstart[c0 + 1]);
                        for (int p = q0; p < q1; p++) {
                            float4 v = sorted[p];
                            float t = fmaf(v.x, m2x, fmaf(v.y, m2y, fmaf(v.z, m2z, v.w)));
                            best = fminf(best, t);
                        }
                    }
                    if (xb <= G - 1) {
                        int c0 = rowbase + xb;
                        int q0 = __ldg(&cellstart[c0]), q1 = __ldg(&cellstart[c0 + 1]);
                        for (int p = q0; p < q1; p++) {
                            float4 v = sorted[p];
                            float t = fmaf(v.x, m2x, fmaf(v.y, m2y, fmaf(v.z, m2z, v.w)));
                            best = fminf(best, t);
                        }
                    }
                }
            }
        }
        if (szlo == 0 && sylo == 0 && sxlo == 0 &&
            szhi == G - 1 && syhi == G - 1 && sxhi == G - 1) break;
    }
    return fmaxf(best + qw, 0.0f);
}

// ---------------- kernel A: fused init + prep ----------------
__global__ void init_prep_kernel(const float* __restrict__ ov,
                                 const int*   __restrict__ of,
                                 const float* __restrict__ sv,
                                 const int*   __restrict__ sf) {
    int i = blockIdx.x * 256 + threadIdx.x;
    if (i < NCELLS)  { g_count[i] = 0;  g_cursor[i] = 0;
                       g_count3[i] = 0; g_cursor3[i] = 0; }
    if (i < NCELLS2) { g_count2[i] = 0; g_cursor2[i] = 0; }
    if (i == 0) {
        g_maxbits = 0u;
        g_done = 0u;
        g_scan_arrive = 0;
        for (int k = 0; k < 3; k++) { g_bbox[k] = 0xFFFFFFFFu;  g_bbox[k + 3] = 0u; }
        for (int k = 0; k < 3; k++) { g_bbox2[k] = 0xFFFFFFFFu; g_bbox2[k + 3] = 0u; }
    }

    // bbox of original vertices
    {
        float mnx =  3.0e38f, mxx = -3.0e38f;
        float mny =  3.0e38f, mxy = -3.0e38f;
        float mnz =  3.0e38f, mxz = -3.0e38f;
        if (i < N_OV) {
            mnx = mxx = ov[3 * i];
            mny = mxy = ov[3 * i + 1];
            mnz = mxz = ov[3 * i + 2];
        }
#pragma unroll
        for (int o = 16; o > 0; o >>= 1) {
            mnx = fminf(mnx, __shfl_xor_sync(0xffffffffu, mnx, o));
            mny = fminf(mny, __shfl_xor_sync(0xffffffffu, mny, o));
            mnz = fminf(mnz, __shfl_xor_sync(0xffffffffu, mnz, o));
            mxx = fmaxf(mxx, __shfl_xor_sync(0xffffffffu, mxx, o));
            mxy = fmaxf(mxy, __shfl_xor_sync(0xffffffffu, mxy, o));
            mxz = fmaxf(mxz, __shfl_xor_sync(0xffffffffu, mxz, o));
        }
        if ((threadIdx.x & 31) == 0 && (blockIdx.x * 256 + (threadIdx.x & ~31)) < N_OV) {
            atomicMin(&g_bbox[0], f2o(mnx));
            atomicMin(&g_bbox[1], f2o(mny));
            atomicMin(&g_bbox[2], f2o(mnz));
            atomicMax(&g_bbox[3], f2o(mxx));
            atomicMax(&g_bbox[4], f2o(mxy));
            atomicMax(&g_bbox[5], f2o(mxz));
        }
    }
    // original barycenters + their bbox
    {
        float bx, by, bz;
        float mnx =  3.0e38f, mxx = -3.0e38f;
        float mny =  3.0e38f, mxy = -3.0e38f;
        float mnz =  3.0e38f, mxz = -3.0e38f;
        if (i < N_OF) {
            int f0 = of[3 * i], f1 = of[3 * i + 1], f2 = of[3 * i + 2];
            bx = (ov[3 * f0] + ov[3 * f1] + ov[3 * f2]) / 3.0f;
            by = (ov[3 * f0 + 1] + ov[3 * f1 + 1] + ov[3 * f2 + 1]) / 3.0f;
            bz = (ov[3 * f0 + 2] + ov[3 * f1 + 2] + ov[3 * f2 + 2]) / 3.0f;
            g_obp[i] = make_float4(bx, by, bz, bx * bx + by * by + bz * bz);
            mnx = mxx = bx; mny = mxy = by; mnz = mxz = bz;
        }
#pragma unroll
        for (int o = 16; o > 0; o >>= 1) {
            mnx = fminf(mnx, __shfl_xor_sync(0xffffffffu, mnx, o));
            mny = fminf(mny, __shfl_xor_sync(0xffffffffu, mny, o));
            mnz = fminf(mnz, __shfl_xor_sync(0xffffffffu, mnz, o));
            mxx = fmaxf(mxx, __shfl_xor_sync(0xffffffffu, mxx, o));
            mxy = fmaxf(mxy, __shfl_xor_sync(0xffffffffu, mxy, o));
            mxz = fmaxf(mxz, __shfl_xor_sync(0xffffffffu, mxz, o));
        }
        if ((threadIdx.x & 31) == 0 && (blockIdx.x * 256 + (threadIdx.x & ~31)) < N_OF) {
            atomicMin(&g_bbox2[0], f2o(mnx));
            atomicMin(&g_bbox2[1], f2o(mny));
            atomicMin(&g_bbox2[2], f2o(mnz));
            atomicMax(&g_bbox2[3], f2o(mxx));
            atomicMax(&g_bbox2[4], f2o(mxy));
            atomicMax(&g_bbox2[5], f2o(mxz));
        }
    }
    if (i < N_SF) {
        int f0 = sf[3 * i], f1 = sf[3 * i + 1], f2 = sf[3 * i + 2];
        float bx = (sv[3 * f0] + sv[3 * f1] + sv[3 * f2]) / 3.0f;
        float by = (sv[3 * f0 + 1] + sv[3 * f1 + 1] + sv[3 * f2 + 1]) / 3.0f;
        float bz = (sv[3 * f0 + 2] + sv[3 * f1 + 2] + sv[3 * f2 + 2]) / 3.0f;
        g_sb[i] = make_float4(bx, by, bz, bx * bx + by * by + bz * bz);
    }
}

// ---------------- kernel B: sample gen + ALL cell counts ----------------
__global__ void gen_count_kernel(const float* __restrict__ ov,
                                 const float* __restrict__ sv,
                                 const int*   __restrict__ sf) {
    int j = blockIdx.x * 256 + threadIdx.x;

    if (j < N_SAMPLES) {
        U2 ua = threefry2x32(RK1.a, RK1.b, 0u, (uint32_t)j);
        U2 ub = threefry2x32(RK2.a, RK2.b, 0u, (uint32_t)j);

        float u1 = bits_to_uniform(ua.a ^ ua.b);
        float r2 = bits_to_uniform(ub.a ^ ub.b);
        float sq = sqrtf(u1);
        float a = 1.0f - sq;
        float b = sq * (1.0f - r2);
        float c = sq * r2;
        int f = j / NSAMP;
        int i0 = sf[3 * f], i1 = sf[3 * f + 1], i2 = sf[3 * f + 2];
        float x = a * sv[3 * i0]     + b * sv[3 * i1]     + c * sv[3 * i2];
        float y = a * sv[3 * i0 + 1] + b * sv[3 * i1 + 1] + c * sv[3 * i2 + 1];
        float z = a * sv[3 * i0 + 2] + b * sv[3 * i1 + 2] + c * sv[3 * i2 + 2];
        g_samples[j] = make_float4(x, y, z, x * x + y * y + z * z);

        GridGeom g = load_geom(g_bbox, GRID_G);
        int cx = cell_coord(x, g.x0, g.invh, GRID_G);
        int cy = cell_coord(y, g.y0, g.invh, GRID_G);
        int cz = cell_coord(z, g.z0, g.invh, GRID_G);
        atomicAdd(&g_count3[(cz * GRID_G + cy) * GRID_G + cx], 1);
    }
    if (j < N_OV) {
        GridGeom g = load_geom(g_bbox, GRID_G);
        int cx = cell_coord(ov[3 * j],     g.x0, g.invh, GRID_G);
        int cy = cell_coord(ov[3 * j + 1], g.y0, g.invh, GRID_G);
        int cz = cell_coord(ov[3 * j + 2], g.z0, g.invh, GRID_G);
        atomicAdd(&g_count[(cz * GRID_G + cy) * GRID_G + cx], 1);
    }
    if (j < N_OF) {
        GridGeom g = load_geom(g_bbox2, GRID_G2);
        float4 b = g_obp[j];
        int cx = cell_coord(b.x, g.x0, g.invh, GRID_G2);
        int cy = cell_coord(b.y, g.y0, g.invh, GRID_G2);
        int cz = cell_coord(b.z, g.z0, g.invh, GRID_G2);
        atomicAdd(&g_count2[(cz * GRID_G2 + cy) * GRID_G2 + cx], 1);
    }
}

// ---------------- kernel C: single-launch full scan (3 grids) --------------
// 96 blocks, all co-resident (<=148 SMs) — spin-wait on arrival counter is safe.
__global__ void __launch_bounds__(1024) scan_kernel() {
    int b = blockIdx.x;
    int tid = threadIdx.x;
    const int* cnt;
    int* cs;
    int* bsum;
    int bb;
    int total_idx;
    if (b < SCAN_BLOCKS)                     { cnt = g_count;  cs = g_cellstart;  bsum = g_blocksum;  bb = b;               total_idx = NCELLS; }
    else if (b < SCAN_BLOCKS + SCAN_BLOCKS2) { cnt = g_count2; cs = g_cellstart2; bsum = g_blocksum2; bb = b - SCAN_BLOCKS; total_idx = NCELLS2; }
    else                                     { cnt = g_count3; cs = g_cellstart3; bsum = g_blocksum3; bb = b - SCAN_BLOCKS - SCAN_BLOCKS2; total_idx = NCELLS; }

    __shared__ int sd[1024];
    int cell = bb * 1024 + tid;
    int cv = cnt[cell];
    sd[tid] = cv;
    __syncthreads();
#pragma unroll
    for (int off = 1; off < 1024; off <<= 1) {
        int v = (tid >= off) ? sd[tid - off] : 0;
        __syncthreads();
        sd[tid] += v;
        __syncthreads();
    }
    int local_ex = sd[tid] - cv;

    // publish block sum, then arrive (write fenced by the same thread)
    if (tid == 1023) {
        bsum[bb] = sd[1023];
        __threadfence();
        atomicAdd(&g_scan_arrive, 1);
        while (atomicAdd(&g_scan_arrive, 0) < TOTAL_SCAN_BLOCKS) { }
    }
    __syncthreads();

    // warp-scan of this grid's 32 block sums -> segment offset
    __shared__ int s_off, s_tot;
    if (tid < 32) {
        int v = bsum[tid];
        int s = v;
#pragma unroll
        for (int off = 1; off < 32; off <<= 1) {
            int t = __shfl_up_sync(0xffffffffu, s, off);
            if (tid >= off) s += t;
        }
        if (tid == bb) s_off = s - v;
        if (tid == 31) s_tot = s;
    }
    __syncthreads();
    cs[cell] = local_ex + s_off;
    if (bb == SCAN_BLOCKS - 1 && tid == 0) cs[total_idx] = s_tot;
}

// ---------------- kernel D: scatter (vertices, barycenters, samples) -------
__global__ void scatter_kernel(const float* __restrict__ ov,
                               const float* __restrict__ fp) {
    int i = blockIdx.x * 256 + threadIdx.x;
    if (i < N_OV) {
        GridGeom g = load_geom(g_bbox, GRID_G);
        float x = ov[3 * i], y = ov[3 * i + 1], z = ov[3 * i + 2];
        int cx = cell_coord(x, g.x0, g.invh, GRID_G);
        int cy = cell_coord(y, g.y0, g.invh, GRID_G);
        int cz = cell_coord(z, g.z0, g.invh, GRID_G);
        int c = (cz * GRID_G + cy) * GRID_G + cx;
        int pos = g_cellstart[c] + atomicAdd(&g_cursor[c], 1);
        g_sorted[pos] = make_float4(x, y, z, x * x + y * y + z * z);
    }
    if (i < N_OF) {
        GridGeom g = load_geom(g_bbox2, GRID_G2);
        float4 b = g_obp[i];
        int cx = cell_coord(b.x, g.x0, g.invh, GRID_G2);
        int cy = cell_coord(b.y, g.y0, g.invh, GRID_G2);
        int cz = cell_coord(b.z, g.z0, g.invh, GRID_G2);
        int c = (cz * GRID_G2 + cy) * GRID_G2 + cx;
        int pos = g_cellstart2[c] + atomicAdd(&g_cursor2[c], 1);
        g_sorted2[pos] = b;
    }
    if (i < N_SAMPLES) {
        GridGeom g = load_geom(g_bbox, GRID_G);
        float4 s = g_samples[i];
        int cx = cell_coord(s.x, g.x0, g.invh, GRID_G);
        int cy = cell_coord(s.y, g.y0, g.invh, GRID_G);
        int cz = cell_coord(s.z, g.z0, g.invh, GRID_G);
        int c = (cz * GRID_G + cy) * GRID_G + cx;
        int pos = g_cellstart3[c] + atomicAdd(&g_cursor3[c], 1);
        g_ssorted[pos] = s;
        g_sfp[pos] = fp[i / NSAMP];
    }
}

// ---------------- kernel E: fused forward + reverse + final ----------------
__global__ void __launch_bounds__(256) fused_nn_kernel(const float* __restrict__ fp,
                                                       float* __restrict__ out) {
    int b = blockIdx.x;
    int tid = threadIdx.x;

    if (b < FWD_WARP_BLOCKS) {
        // -------- forward: one warp per simplified barycenter --------
        int warp = (b * 256 + tid) >> 5;
        int lane = tid & 31;
        if (warp < N_SF) {
            GridGeom g = load_geom(g_bbox2, GRID_G2);
            float4 Q = g_sb[warp];
            float m2x = -2.0f * Q.x, m2y = -2.0f * Q.y, m2z = -2.0f * Q.z;
            int cx = cell_coord(Q.x, g.x0, g.invh, GRID_G2);
            int cy = cell_coord(Q.y, g.y0, g.invh, GRID_G2);
            int cz = cell_coord(Q.z, g.z0, g.invh, GRID_G2);
            const int G = GRID_G2;

            float best = 3.0e38f;
            for (int R = 0; R <= G; R++) {
                float bmin = best;
#pragma unroll
                for (int o = 16; o > 0; o >>= 1)
                    bmin = fminf(bmin, __shfl_xor_sync(0xffffffffu, bmin, o));
                if (R > 0) {
                    float lb = (float)(R - 1) * g.h;
                    if (bmin + Q.w <= lb * lb) break;
                }
                int zlo = max(cz - R, 0), zhi = min(cz + R, G - 1);
                int ylo = max(cy - R, 0), yhi = min(cy + R, G - 1);
                int xlo = max(cx - R, 0), xhi = min(cx + R, G - 1);
                for (int z = zlo; z <= zhi; z++) {
                    bool ze = (z == cz - R) || (z == cz + R);
                    for (int y = ylo; y <= yhi; y++) {
                        bool edge = ze || (y == cy - R) || (y == cy + R);
                        int rowbase = (z * G + y) * G;
                        if (edge) {
                            int p0 = __ldg(&g_cellstart2[rowbase + xlo]);
                            int p1 = __ldg(&g_cellstart2[rowbase + xhi + 1]);
                            for (int p = p0 + lane; p < p1; p += 32) {
                                float4 v = g_sorted2[p];
                                float t = fmaf(v.x, m2x, fmaf(v.y, m2y, fmaf(v.z, m2z, v.w)));
                                best = fminf(best, t);
                            }
                        } else {
                            int xa = cx - R, xb = cx + R;
                            if (xa >= 0) {
                                int c0 = rowbase + xa;
                                int p0 = __ldg(&g_cellstart2[c0]), p1 = __ldg(&g_cellstart2[c0 + 1]);
                                for (int p = p0 + lane; p < p1; p += 32) {
                                    float4 v = g_sorted2[p];
                                    float t = fmaf(v.x, m2x, fmaf(v.y, m2y, fmaf(v.z, m2z, v.w)));
                                    best = fminf(best, t);
                                }
                            }
                            if (xb <= G - 1) {
                                int c0 = rowbase + xb;
                                int p0 = __ldg(&g_cellstart2[c0]), p1 = __ldg(&g_cellstart2[c0 + 1]);
                                for (int p = p0 + lane; p < p1; p += 32) {
                                    float4 v = g_sorted2[p];
                                    float t = fmaf(v.x, m2x, fmaf(v.y, m2y, fmaf(v.z, m2z, v.w)));
                                    best = fminf(best, t);
                                }
                            }
                        }
                    }
                }
                if (zlo == 0 && ylo == 0 && xlo == 0 &&
                    zhi == G - 1 && yhi == G - 1 && xhi == G - 1) break;
            }
            float bmin = best;
#pragma unroll
            for (int o = 16; o > 0; o >>= 1)
                bmin = fminf(bmin, __shfl_xor_sync(0xffffffffu, bmin, o));
            if (lane == 0)
                g_minfwd[warp] = __float_as_uint(fmaxf(bmin + Q.w, 0.0f));
        }
    } else {
        // -------- reverse: one thread per cell-sorted sample --------
        int rb = b - FWD_WARP_BLOCKS;
        int j = rb * 256 + tid;

        float d = 0.0f;
        double contrib = 0.0;
        if (j < N_SAMPLES) {
            GridGeom g = load_geom(g_bbox, GRID_G);
            float4 s = g_ssorted[j];
            float d2 = shell_nn<GRID_G>(s.x, s.y, s.z, s.w, g, g_cellstart, g_sorted);
            d = sqrtf(d2);
            contrib = (double)(g_sfp[j] * d);
        }

        __shared__ double rsum[256];
        __shared__ float rmax[256];
        rsum[tid] = contrib;
        rmax[tid] = d;
        __syncthreads();
#pragma unroll
        for (int o = 128; o > 0; o >>= 1) {
            if (tid < o) {
                rsum[tid] += rsum[tid + o];
                rmax[tid] = fmaxf(rmax[tid], rmax[tid + o]);
            }
            __syncthreads();
        }
        if (tid == 0) {
            g_part[rb] = rsum[0];
            atomicMax(&g_maxbits, __float_as_uint(rmax[0]));
        }
    }

    // -------- completion: last block runs the final reduction --------
    __syncthreads();
    __threadfence();
    __shared__ unsigned s_rank;
    if (tid == 0) s_rank = atomicAdd(&g_done, 1u);
    __syncthreads();
    if (s_rank != FUSED_BLOCKS - 1) return;

    __shared__ double red[256];
    double fwd = 0.0, pen = 0.0, rev = 0.0;
    for (int i = tid; i < N_SF; i += 256) {
        float p = fp[i];
        float d2 = __uint_as_float(g_minfwd[i]);
        fwd += (double)(p * sqrtf(d2));
        pen += (double)(1.0f - p);
    }
    for (int k = tid; k < REV_BLOCKS; k += 256) rev += g_part[k];

    double totF, totP, totR;
    red[tid] = fwd; __syncthreads();
#pragma unroll
    for (int o = 128; o > 0; o >>= 1) { if (tid < o) red[tid] += red[tid + o]; __syncthreads(); }
    totF = red[0]; __syncthreads();
    red[tid] = pen; __syncthreads();
#pragma unroll
    for (int o = 128; o > 0; o >>= 1) { if (tid < o) red[tid] += red[tid + o]; __syncthreads(); }
    totP = red[0]; __syncthreads();
    red[tid] = rev; __syncthreads();
#pragma unroll
    for (int o = 128; o > 0; o >>= 1) { if (tid < o) red[tid] += red[tid + o]; __syncthreads(); }
    totR = red[0];

    if (tid == 0) {
        double maxd = (double)__uint_as_float(g_maxbits);
        double result = totF + 1e-4 * totP + totR / (maxd + 1e-8) * 0.1;
        out[0] = (float)result;
    }
}

// ---------------- launch ----------------
extern "C" void kernel_launch(void* const* d_in, const int* in_sizes, int n_in,
                              void* d_out, int out_size) {
    const float* ov = (const float*)d_in[0];
    const int*   of = (const int*)  d_in[1];
    const float* sv = (const float*)d_in[2];
    const int*   sf = (const int*)  d_in[3];
    const float* fp = (const float*)d_in[4];
    float* out = (float*)d_out;

    init_prep_kernel<<<(NCELLS + 255) / 256, 256>>>(ov, of, sv, sf);
    gen_count_kernel<<<GEN_BLOCKS, 256>>>(ov, sv, sf);
    scan_kernel<<<TOTAL_SCAN_BLOCKS, 1024>>>();
    scatter_kernel<<<GEN_BLOCKS, 256>>>(ov, fp);
    fused_nn_kernel<<<FUSED_BLOCKS, 256>>>(fp, out);
}

// round 15
// speedup vs baseline: 1.2331x; 1.0744x over previous
#include <cuda_runtime.h>
#include <cuda_bf16.h>
#include <stdint.h>

// ---------------- problem constants (static shapes) ----------------
#define N_OV 20000
#define N_OF 30000
#define N_SV 4000
#define N_SF 5000
#define NSAMP 50
#define N_SAMPLES 250000
// vertex grid (reverse term) — also used to sort samples
#define GRID_G 32
#define NCELLS (GRID_G * GRID_G * GRID_G)       // 32768
#define SCAN_BLOCKS 32
// barycenter grid (forward term)
#define GRID_G2 32
#define NCELLS2 (GRID_G2 * GRID_G2 * GRID_G2)   // 32768
#define SCAN_BLOCKS2 32
#define REV_BLOCKS 977                           // ceil(250000/256)
#define FWD_WARP_BLOCKS 625                      // 5000 warps
#define FUSED_BLOCKS (FWD_WARP_BLOCKS + REV_BLOCKS)
#define GEN_BLOCKS 977
#define TOTAL_SCAN_BLOCKS 96

// ---------------- device scratch (static, no runtime alloc) ----------------
__device__ float4    g_obp[N_OF];
__device__ float4    g_sb[N_SF];
__device__ unsigned  g_minfwd[N_SF];
__device__ float4    g_samples[N_SAMPLES];
__device__ float4    g_ssorted[N_SAMPLES];
__device__ float     g_sfp[N_SAMPLES];
__device__ unsigned  g_maxbits;
__device__ double    g_part[REV_BLOCKS];
__device__ unsigned  g_done;
__device__ int       g_scan_arrive;
// (cell, rank) recorded during the count pass -> atomic-free scatter
__device__ int       g_vcell[N_OV];
__device__ int       g_vrank[N_OV];
__device__ int       g_bcell[N_OF];
__device__ int       g_brank[N_OF];
__device__ int       g_scell[N_SAMPLES];
__device__ int       g_srank[N_SAMPLES];
// grid V (vertices)
__device__ unsigned  g_bbox[6];
__device__ int       g_count[NCELLS];
__device__ int       g_cellstart[NCELLS + 1];
__device__ int       g_blocksum[SCAN_BLOCKS];
__device__ float4    g_sorted[N_OV];
// grid B (original barycenters)
__device__ unsigned  g_bbox2[6];
__device__ int       g_count2[NCELLS2];
__device__ int       g_cellstart2[NCELLS2 + 1];
__device__ int       g_blocksum2[SCAN_BLOCKS2];
__device__ float4    g_sorted2[N_OF];
// grid S (samples, same geometry as grid V)
__device__ int       g_count3[NCELLS];
__device__ int       g_cellstart3[NCELLS + 1];
__device__ int       g_blocksum3[SCAN_BLOCKS];

// ---------------- ordered-float helpers ----------------
__device__ __forceinline__ unsigned f2o(float f) {
    unsigned u = __float_as_uint(f);
    return (u & 0x80000000u) ? ~u : (u | 0x80000000u);
}
__device__ __forceinline__ float o2f(unsigned u) {
    u = (u & 0x80000000u) ? (u & 0x7fffffffu) : ~u;
    return __uint_as_float(u);
}

// ---------------- threefry2x32 (JAX partitionable, 20 rounds) ----------------
__host__ __device__ constexpr uint32_t rotl32(uint32_t x, int r) {
    return (x << r) | (x >> (32 - r));
}
struct U2 { uint32_t a, b; };
__host__ __device__ constexpr U2 threefry2x32(uint32_t k0, uint32_t k1,
                                              uint32_t x0, uint32_t x1) {
    uint32_t ks0 = k0, ks1 = k1, ks2 = k0 ^ k1 ^ 0x1BD11BDAu;
    x0 += ks0; x1 += ks1;
    x0 += x1; x1 = rotl32(x1, 13); x1 ^= x0;
    x0 += x1; x1 = rotl32(x1, 15); x1 ^= x0;
    x0 += x1; x1 = rotl32(x1, 26); x1 ^= x0;
    x0 += x1; x1 = rotl32(x1,  6); x1 ^= x0;
    x0 += ks1; x1 += ks2 + 1u;
    x0 += x1; x1 = rotl32(x1, 17); x1 ^= x0;
    x0 += x1; x1 = rotl32(x1, 29); x1 ^= x0;
    x0 += x1; x1 = rotl32(x1, 16); x1 ^= x0;
    x0 += x1; x1 = rotl32(x1, 24); x1 ^= x0;
    x0 += ks2; x1 += ks0 + 2u;
    x0 += x1; x1 = rotl32(x1, 13); x1 ^= x0;
    x0 += x1; x1 = rotl32(x1, 15); x1 ^= x0;
    x0 += x1; x1 = rotl32(x1, 26); x1 ^= x0;
    x0 += x1; x1 = rotl32(x1,  6); x1 ^= x0;
    x0 += ks0; x1 += ks1 + 3u;
    x0 += x1; x1 = rotl32(x1, 17); x1 ^= x0;
    x0 += x1; x1 = rotl32(x1, 29); x1 ^= x0;
    x0 += x1; x1 = rotl32(x1, 16); x1 ^= x0;
    x0 += x1; x1 = rotl32(x1, 24); x1 ^= x0;
    x0 += ks1; x1 += ks2 + 4u;
    x0 += x1; x1 = rotl32(x1, 13); x1 ^= x0;
    x0 += x1; x1 = rotl32(x1, 15); x1 ^= x0;
    x0 += x1; x1 = rotl32(x1, 26); x1 ^= x0;
    x0 += x1; x1 = rotl32(x1,  6); x1 ^= x0;
    x0 += ks2; x1 += ks0 + 5u;
    return {x0, x1};
}
constexpr U2 RK1 = threefry2x32(0u, 42u, 0u, 0u);
constexpr U2 RK2 = threefry2x32(0u, 42u, 0u, 1u);

__device__ __forceinline__ float bits_to_uniform(uint32_t bits) {
    return __uint_as_float((bits >> 9) | 0x3f800000u) - 1.0f;
}

// ---------------- grid geometry ----------------
struct GridGeom { float x0, y0, z0, invh, h; };
__device__ __forceinline__ GridGeom load_geom(const unsigned* bbox, int G) {
    GridGeom g;
    g.x0 = o2f(bbox[0]); g.y0 = o2f(bbox[1]); g.z0 = o2f(bbox[2]);
    float ex = o2f(bbox[3]) - g.x0;
    float ey = o2f(bbox[4]) - g.y0;
    float ez = o2f(bbox[5]) - g.z0;
    float e = fmaxf(fmaxf(ex, ey), fmaxf(ez, 1e-20f));
    g.h = e / (float)G;
    g.invh = (float)G / e;
    return g;
}
__device__ __forceinline__ int cell_coord(float v, float v0, float invh, int G) {
    int c = (int)((v - v0) * invh);
    return min(max(c, 0), G - 1);
}

// ---------------- exact 1-NN: unrolled 3^3 box (MLP) + shells R>=2 ---------
template <int G>
__device__ __forceinline__ float shell_nn(float qx, float qy, float qz, float qw,
                                          const GridGeom g,
                                          const int* __restrict__ cellstart,
                                          const float4* __restrict__ sorted) {
    float m2x = -2.0f * qx, m2y = -2.0f * qy, m2z = -2.0f * qz;
    int cx = cell_coord(qx, g.x0, g.invh, G);
    int cy = cell_coord(qy, g.y0, g.invh, G);
    int cz = cell_coord(qz, g.z0, g.invh, G);

    // ---- unrolled 3x3x3 box: 9 row segments, all bounds loaded up front ----
    int xlo = max(cx - 1, 0), xhi = min(cx + 1, G - 1);
    int ys[3], zs[3];
    ys[0] = max(cy - 1, 0); ys[1] = cy; ys[2] = min(cy + 1, G - 1);
    zs[0] = max(cz - 1, 0); zs[1] = cz; zs[2] = min(cz + 1, G - 1);
    int p0[9], p1[9];
#pragma unroll
    for (int a = 0; a < 3; a++) {
#pragma unroll
        for (int q = 0; q < 3; q++) {
            int rowbase = (zs[a] * G + ys[q]) * G;
            p0[a * 3 + q] = __ldg(&cellstart[rowbase + xlo]);
            p1[a * 3 + q] = __ldg(&cellstart[rowbase + xhi + 1]);
        }
    }
    float best = 3.0e38f;
#pragma unroll
    for (int r = 0; r < 9; r++) {
        for (int p = p0[r]; p < p1[r]; p++) {
            float4 v = sorted[p];
            float t = fmaf(v.x, m2x, fmaf(v.y, m2y, fmaf(v.z, m2z, v.w)));
            best = fminf(best, t);
        }
    }

    // ---- expanding shells R >= 2 (box == R<=1 complete) ----
    for (int R = 2; R <= G; R++) {
        float lb = (float)(R - 1) * g.h;
        if (best + qw <= lb * lb) break;
        int szlo = max(cz - R, 0), szhi = min(cz + R, G - 1);
        int sylo = max(cy - R, 0), syhi = min(cy + R, G - 1);
        int sxlo = max(cx - R, 0), sxhi = min(cx + R, G - 1);
        for (int z = szlo; z <= szhi; z++) {
            bool ze = (z == cz - R) || (z == cz + R);
            for (int y = sylo; y <= syhi; y++) {
                bool edge = ze || (y == cy - R) || (y == cy + R);
                int rowbase = (z * G + y) * G;
                if (edge) {
                    int q0 = __ldg(&cellstart[rowbase + sxlo]);
                    int q1 = __ldg(&cellstart[rowbase + sxhi + 1]);
                    for (int p = q0; p < q1; p++) {
                        float4 v = sorted[p];
                        float t = fmaf(v.x, m2x, fmaf(v.y, m2y, fmaf(v.z, m2z, v.w)));
                        best = fminf(best, t);
                    }
                } else {
                    int xa = cx - R, xb = cx + R;
                    if (xa >= 0) {
                        int c0 = rowbase + xa;
                        int q0 = __ldg(&cellstart[c0]), q1 = __ldg(&cellstart[c0 + 1]);
                        for (int p = q0; p < q1; p++) {
                            float4 v = sorted[p];
                            float t = fmaf(v.x, m2x, fmaf(v.y, m2y, fmaf(v.z, m2z, v.w)));
                            best = fminf(best, t);
                        }
                    }
                    if (xb <= G - 1) {
                        int c0 = rowbase + xb;
                        int q0 = __ldg(&cellstart[c0]), q1 = __ldg(&cellstart[c0 + 1]);
                        for (int p = q0; p < q1; p++) {
                            float4 v = sorted[p];
                            float t = fmaf(v.x, m2x, fmaf(v.y, m2y, fmaf(v.z, m2z, v.w)));
                            best = fminf(best, t);
                        }
                    }
                }
            }
        }
        if (szlo == 0 && sylo == 0 && sxlo == 0 &&
            szhi == G - 1 && syhi == G - 1 && sxhi == G - 1) break;
    }
    return fmaxf(best + qw, 0.0f);
}

// ---------------- kernel A: fused init + prep ----------------
__global__ void init_prep_kernel(const float* __restrict__ ov,
                                 const int*   __restrict__ of,
                                 const float* __restrict__ sv,
                                 const int*   __restrict__ sf) {
    int i = blockIdx.x * 256 + threadIdx.x;
    if (i < NCELLS)  { g_count[i] = 0; g_count3[i] = 0; }
    if (i < NCELLS2) { g_count2[i] = 0; }
    if (i == 0) {
        g_maxbits = 0u;
        g_done = 0u;
        g_scan_arrive = 0;
        for (int k = 0; k < 3; k++) { g_bbox[k] = 0xFFFFFFFFu;  g_bbox[k + 3] = 0u; }
        for (int k = 0; k < 3; k++) { g_bbox2[k] = 0xFFFFFFFFu; g_bbox2[k + 3] = 0u; }
    }

    // bbox of original vertices
    {
        float mnx =  3.0e38f, mxx = -3.0e38f;
        float mny =  3.0e38f, mxy = -3.0e38f;
        float mnz =  3.0e38f, mxz = -3.0e38f;
        if (i < N_OV) {
            mnx = mxx = ov[3 * i];
            mny = mxy = ov[3 * i + 1];
            mnz = mxz = ov[3 * i + 2];
        }
#pragma unroll
        for (int o = 16; o > 0; o >>= 1) {
            mnx = fminf(mnx, __shfl_xor_sync(0xffffffffu, mnx, o));
            mny = fminf(mny, __shfl_xor_sync(0xffffffffu, mny, o));
            mnz = fminf(mnz, __shfl_xor_sync(0xffffffffu, mnz, o));
            mxx = fmaxf(mxx, __shfl_xor_sync(0xffffffffu, mxx, o));
            mxy = fmaxf(mxy, __shfl_xor_sync(0xffffffffu, mxy, o));
            mxz = fmaxf(mxz, __shfl_xor_sync(0xffffffffu, mxz, o));
        }
        if ((threadIdx.x & 31) == 0 && (blockIdx.x * 256 + (threadIdx.x & ~31)) < N_OV) {
            atomicMin(&g_bbox[0], f2o(mnx));
            atomicMin(&g_bbox[1], f2o(mny));
            atomicMin(&g_bbox[2], f2o(mnz));
            atomicMax(&g_bbox[3], f2o(mxx));
            atomicMax(&g_bbox[4], f2o(mxy));
            atomicMax(&g_bbox[5], f2o(mxz));
        }
    }
    // original barycenters + their bbox
    {
        float bx, by, bz;
        float mnx =  3.0e38f, mxx = -3.0e38f;
        float mny =  3.0e38f, mxy = -3.0e38f;
        float mnz =  3.0e38f, mxz = -3.0e38f;
        if (i < N_OF) {
            int f0 = of[3 * i], f1 = of[3 * i + 1], f2 = of[3 * i + 2];
            bx = (ov[3 * f0] + ov[3 * f1] + ov[3 * f2]) / 3.0f;
            by = (ov[3 * f0 + 1] + ov[3 * f1 + 1] + ov[3 * f2 + 1]) / 3.0f;
            bz = (ov[3 * f0 + 2] + ov[3 * f1 + 2] + ov[3 * f2 + 2]) / 3.0f;
            g_obp[i] = make_float4(bx, by, bz, bx * bx + by * by + bz * bz);
            mnx = mxx = bx; mny = mxy = by; mnz = mxz = bz;
        }
#pragma unroll
        for (int o = 16; o > 0; o >>= 1) {
            mnx = fminf(mnx, __shfl_xor_sync(0xffffffffu, mnx, o));
            mny = fminf(mny, __shfl_xor_sync(0xffffffffu, mny, o));
            mnz = fminf(mnz, __shfl_xor_sync(0xffffffffu, mnz, o));
            mxx = fmaxf(mxx, __shfl_xor_sync(0xffffffffu, mxx, o));
            mxy = fmaxf(mxy, __shfl_xor_sync(0xffffffffu, mxy, o));
            mxz = fmaxf(mxz, __shfl_xor_sync(0xffffffffu, mxz, o));
        }
        if ((threadIdx.x & 31) == 0 && (blockIdx.x * 256 + (threadIdx.x & ~31)) < N_OF) {
            atomicMin(&g_bbox2[0], f2o(mnx));
            atomicMin(&g_bbox2[1], f2o(mny));
            atomicMin(&g_bbox2[2], f2o(mnz));
            atomicMax(&g_bbox2[3], f2o(mxx));
            atomicMax(&g_bbox2[4], f2o(mxy));
            atomicMax(&g_bbox2[5], f2o(mxz));
        }
    }
    if (i < N_SF) {
        int f0 = sf[3 * i], f1 = sf[3 * i + 1], f2 = sf[3 * i + 2];
        float bx = (sv[3 * f0] + sv[3 * f1] + sv[3 * f2]) / 3.0f;
        float by = (sv[3 * f0 + 1] + sv[3 * f1 + 1] + sv[3 * f2 + 1]) / 3.0f;
        float bz = (sv[3 * f0 + 2] + sv[3 * f1 + 2] + sv[3 * f2 + 2]) / 3.0f;
        g_sb[i] = make_float4(bx, by, bz, bx * bx + by * by + bz * bz);
    }
}

// ---------------- kernel B: sample gen + counts, recording (cell, rank) ----
__global__ void gen_count_kernel(const float* __restrict__ ov,
                                 const float* __restrict__ sv,
                                 const int*   __restrict__ sf) {
    int j = blockIdx.x * 256 + threadIdx.x;

    if (j < N_SAMPLES) {
        U2 ua = threefry2x32(RK1.a, RK1.b, 0u, (uint32_t)j);
        U2 ub = threefry2x32(RK2.a, RK2.b, 0u, (uint32_t)j);

        float u1 = bits_to_uniform(ua.a ^ ua.b);
        float r2 = bits_to_uniform(ub.a ^ ub.b);
        float sq = sqrtf(u1);
        float a = 1.0f - sq;
        float b = sq * (1.0f - r2);
        float c = sq * r2;
        int f = j / NSAMP;
        int i0 = sf[3 * f], i1 = sf[3 * f + 1], i2 = sf[3 * f + 2];
        float x = a * sv[3 * i0]     + b * sv[3 * i1]     + c * sv[3 * i2];
        float y = a * sv[3 * i0 + 1] + b * sv[3 * i1 + 1] + c * sv[3 * i2 + 1];
        float z = a * sv[3 * i0 + 2] + b * sv[3 * i1 + 2] + c * sv[3 * i2 + 2];
        g_samples[j] = make_float4(x, y, z, x * x + y * y + z * z);

        GridGeom g = load_geom(g_bbox, GRID_G);
        int cx = cell_coord(x, g.x0, g.invh, GRID_G);
        int cy = cell_coord(y, g.y0, g.invh, GRID_G);
        int cz = cell_coord(z, g.z0, g.invh, GRID_G);
        int c3 = (cz * GRID_G + cy) * GRID_G + cx;
        int rank = atomicAdd(&g_count3[c3], 1);
        g_scell[j] = c3;
        g_srank[j] = rank;
    }
    if (j < N_OV) {
        GridGeom g = load_geom(g_bbox, GRID_G);
        int cx = cell_coord(ov[3 * j],     g.x0, g.invh, GRID_G);
        int cy = cell_coord(ov[3 * j + 1], g.y0, g.invh, GRID_G);
        int cz = cell_coord(ov[3 * j + 2], g.z0, g.invh, GRID_G);
        int c = (cz * GRID_G + cy) * GRID_G + cx;
        int rank = atomicAdd(&g_count[c], 1);
        g_vcell[j] = c;
        g_vrank[j] = rank;
    }
    if (j < N_OF) {
        GridGeom g = load_geom(g_bbox2, GRID_G2);
        float4 b = g_obp[j];
        int cx = cell_coord(b.x, g.x0, g.invh, GRID_G2);
        int cy = cell_coord(b.y, g.y0, g.invh, GRID_G2);
        int cz = cell_coord(b.z, g.z0, g.invh, GRID_G2);
        int c = (cz * GRID_G2 + cy) * GRID_G2 + cx;
        int rank = atomicAdd(&g_count2[c], 1);
        g_bcell[j] = c;
        g_brank[j] = rank;
    }
}

// ---------------- kernel C: single-launch full scan (3 grids) --------------
// 96 blocks, all co-resident (<=148 SMs) — spin-wait on arrival counter is safe.
__global__ void __launch_bounds__(1024) scan_kernel() {
    int b = blockIdx.x;
    int tid = threadIdx.x;
    const int* cnt;
    int* cs;
    int* bsum;
    int bb;
    int total_idx;
    if (b < SCAN_BLOCKS)                     { cnt = g_count;  cs = g_cellstart;  bsum = g_blocksum;  bb = b;               total_idx = NCELLS; }
    else if (b < SCAN_BLOCKS + SCAN_BLOCKS2) { cnt = g_count2; cs = g_cellstart2; bsum = g_blocksum2; bb = b - SCAN_BLOCKS; total_idx = NCELLS2; }
    else                                     { cnt = g_count3; cs = g_cellstart3; bsum = g_blocksum3; bb = b - SCAN_BLOCKS - SCAN_BLOCKS2; total_idx = NCELLS; }

    __shared__ int sd[1024];
    int cell = bb * 1024 + tid;
    int cv = cnt[cell];
    sd[tid] = cv;
    __syncthreads();
#pragma unroll
    for (int off = 1; off < 1024; off <<= 1) {
        int v = (tid >= off) ? sd[tid - off] : 0;
        __syncthreads();
        sd[tid] += v;
        __syncthreads();
    }
    int local_ex = sd[tid] - cv;

    if (tid == 1023) {
        bsum[bb] = sd[1023];
        __threadfence();
        atomicAdd(&g_scan_arrive, 1);
        while (atomicAdd(&g_scan_arrive, 0) < TOTAL_SCAN_BLOCKS) { }
    }
    __syncthreads();

    __shared__ int s_off, s_tot;
    if (tid < 32) {
        int v = bsum[tid];
        int s = v;
#pragma unroll
        for (int off = 1; off < 32; off <<= 1) {
            int t = __shfl_up_sync(0xffffffffu, s, off);
            if (tid >= off) s += t;
        }
        if (tid == bb) s_off = s - v;
        if (tid == 31) s_tot = s;
    }
    __syncthreads();
    cs[cell] = local_ex + s_off;
    if (bb == SCAN_BLOCKS - 1 && tid == 0) cs[total_idx] = s_tot;
}

// ---------------- kernel D: atomic-free scatter ----------------
__global__ void scatter_kernel(const float* __restrict__ ov,
                               const float* __restrict__ fp) {
    int i = blockIdx.x * 256 + threadIdx.x;
    if (i < N_OV) {
        float x = ov[3 * i], y = ov[3 * i + 1], z = ov[3 * i + 2];
        int pos = __ldg(&g_cellstart[g_vcell[i]]) + g_vrank[i];
        g_sorted[pos] = make_float4(x, y, z, x * x + y * y + z * z);
    }
    if (i < N_OF) {
        int pos = __ldg(&g_cellstart2[g_bcell[i]]) + g_brank[i];
        g_sorted2[pos] = g_obp[i];
    }
    if (i < N_SAMPLES) {
        int pos = __ldg(&g_cellstart3[g_scell[i]]) + g_srank[i];
        g_ssorted[pos] = g_samples[i];
        g_sfp[pos] = fp[i / NSAMP];
    }
}

// ---------------- kernel E: fused forward + reverse + final ----------------
__global__ void __launch_bounds__(256) fused_nn_kernel(const float* __restrict__ fp,
                                                       float* __restrict__ out) {
    int b = blockIdx.x;
    int tid = threadIdx.x;

    if (b < FWD_WARP_BLOCKS) {
        // -------- forward: one warp per simplified barycenter --------
        int warp = (b * 256 + tid) >> 5;
        int lane = tid & 31;
        if (warp < N_SF) {
            GridGeom g = load_geom(g_bbox2, GRID_G2);
            float4 Q = g_sb[warp];
            float m2x = -2.0f * Q.x, m2y = -2.0f * Q.y, m2z = -2.0f * Q.z;
            int cx = cell_coord(Q.x, g.x0, g.invh, GRID_G2);
            int cy = cell_coord(Q.y, g.y0, g.invh, GRID_G2);
            int cz = cell_coord(Q.z, g.z0, g.invh, GRID_G2);
            const int G = GRID_G2;

            float best = 3.0e38f;
            for (int R = 0; R <= G; R++) {
                float bmin = best;
#pragma unroll
                for (int o = 16; o > 0; o >>= 1)
                    bmin = fminf(bmin, __shfl_xor_sync(0xffffffffu, bmin, o));
                if (R > 0) {
                    float lb = (float)(R - 1) * g.h;
                    if (bmin + Q.w <= lb * lb) break;
                }
                int zlo = max(cz - R, 0), zhi = min(cz + R, G - 1);
                int ylo = max(cy - R, 0), yhi = min(cy + R, G - 1);
                int xlo = max(cx - R, 0), xhi = min(cx + R, G - 1);
                for (int z = zlo; z <= zhi; z++) {
                    bool ze = (z == cz - R) || (z == cz + R);
                    for (int y = ylo; y <= yhi; y++) {
                        bool edge = ze || (y == cy - R) || (y == cy + R);
                        int rowbase = (z * G + y) * G;
                        if (edge) {
                            int p0 = __ldg(&g_cellstart2[rowbase + xlo]);
                            int p1 = __ldg(&g_cellstart2[rowbase + xhi + 1]);
                            for (int p = p0 + lane; p < p1; p += 32) {
                                float4 v = g_sorted2[p];
                                float t = fmaf(v.x, m2x, fmaf(v.y, m2y, fmaf(v.z, m2z, v.w)));
                                best = fminf(best, t);
                            }
                        } else {
                            int xa = cx - R, xb = cx + R;
                            if (xa >= 0) {
                                int c0 = rowbase + xa;
                                int p0 = __ldg(&g_cellstart2[c0]), p1 = __ldg(&g_cellstart2[c0 + 1]);
                                for (int p = p0 + lane; p < p1; p += 32) {
                                    float4 v = g_sorted2[p];
                                    float t = fmaf(v.x, m2x, fmaf(v.y, m2y, fmaf(v.z, m2z, v.w)));
                                    best = fminf(best, t);
                                }
                            }
                            if (xb <= G - 1) {
                                int c0 = rowbase + xb;
                                int p0 = __ldg(&g_cellstart2[c0]), p1 = __ldg(&g_cellstart2[c0 + 1]);
                                for (int p = p0 + lane; p < p1; p += 32) {
                                    float4 v = g_sorted2[p];
                                    float t = fmaf(v.x, m2x, fmaf(v.y, m2y, fmaf(v.z, m2z, v.w)));
                                    best = fminf(best, t);
                                }
                            }
                        }
                    }
                }
                if (zlo == 0 && ylo == 0 && xlo == 0 &&
                    zhi == G - 1 && yhi == G - 1 && xhi == G - 1) break;
            }
            float bmin = best;
#pragma unroll
            for (int o = 16; o > 0; o >>= 1)
                bmin = fminf(bmin, __shfl_xor_sync(0xffffffffu, bmin, o));
            if (lane == 0)
                g_minfwd[warp] = __float_as_uint(fmaxf(bmin + Q.w, 0.0f));
        }
    } else {
        // -------- reverse: one thread per cell-sorted sample --------
        int rb = b - FWD_WARP_BLOCKS;
        int j = rb * 256 + tid;

        float d = 0.0f;
        double contrib = 0.0;
        if (j < N_SAMPLES) {
            GridGeom g = load_geom(g_bbox, GRID_G);
            float4 s = g_ssorted[j];
            float d2 = shell_nn<GRID_G>(s.x, s.y, s.z, s.w, g, g_cellstart, g_sorted);
            d = sqrtf(d2);
            contrib = (double)(g_sfp[j] * d);
        }

        __shared__ double rsum[256];
        __shared__ float rmax[256];
        rsum[tid] = contrib;
        rmax[tid] = d;
        __syncthreads();
#pragma unroll
        for (int o = 128; o > 0; o >>= 1) {
            if (tid < o) {
                rsum[tid] += rsum[tid + o];
                rmax[tid] = fmaxf(rmax[tid], rmax[tid + o]);
            }
            __syncthreads();
        }
        if (tid == 0) {
            g_part[rb] = rsum[0];
            atomicMax(&g_maxbits, __float_as_uint(rmax[0]));
        }
    }

    // -------- completion: last block runs the final reduction --------
    __syncthreads();
    __threadfence();
    __shared__ unsigned s_rank;
    if (tid == 0) s_rank = atomicAdd(&g_done, 1u);
    __syncthreads();
    if (s_rank != FUSED_BLOCKS - 1) return;

    __shared__ double red[256];
    double fwd = 0.0, pen = 0.0, rev = 0.0;
    for (int i = tid; i < N_SF; i += 256) {
        float p = fp[i];
        float d2 = __uint_as_float(g_minfwd[i]);
        fwd += (double)(p * sqrtf(d2));
        pen += (double)(1.0f - p);
    }
    for (int k = tid; k < REV_BLOCKS; k += 256) rev += g_part[k];

    double totF, totP, totR;
    red[tid] = fwd; __syncthreads();
#pragma unroll
    for (int o = 128; o > 0; o >>= 1) { if (tid < o) red[tid] += red[tid + o]; __syncthreads(); }
    totF = red[0]; __syncthreads();
    red[tid] = pen; __syncthreads();
#pragma unroll
    for (int o = 128; o > 0; o >>= 1) { if (tid < o) red[tid] += red[tid + o]; __syncthreads(); }
    totP = red[0]; __syncthreads();
    red[tid] = rev; __syncthreads();
#pragma unroll
    for (int o = 128; o > 0; o >>= 1) { if (tid < o) red[tid] += red[tid + o]; __syncthreads(); }
    totR = red[0];

    if (tid == 0) {
        double maxd = (double)__uint_as_float(g_maxbits);
        double result = totF + 1e-4 * totP + totR / (maxd + 1e-8) * 0.1;
        out[0] = (float)result;
    }
}

// ---------------- launch ----------------
extern "C" void kernel_launch(void* const* d_in, const int* in_sizes, int n_in,
                              void* d_out, int out_size) {
    const float* ov = (const float*)d_in[0];
    const int*   of = (const int*)  d_in[1];
    const float* sv = (const float*)d_in[2];
    const int*   sf = (const int*)  d_in[3];
    const float* fp = (const float*)d_in[4];
    float* out = (float*)d_out;

    init_prep_kernel<<<(NCELLS + 255) / 256, 256>>>(ov, of, sv, sf);
    gen_count_kernel<<<GEN_BLOCKS, 256>>>(ov, sv, sf);
    scan_kernel<<<TOTAL_SCAN_BLOCKS, 1024>>>();
    scatter_kernel<<<GEN_BLOCKS, 256>>>(ov, fp);
    fused_nn_kernel<<<FUSED_BLOCKS, 256>>>(fp, out);
}

// round 16
// speedup vs baseline: 1.2738x; 1.0331x over previous
#include <cuda_runtime.h>
#include <cuda_bf16.h>
#include <stdint.h>

// ---------------- problem constants (static shapes) ----------------
#define N_OV 20000
#define N_OF 30000
#define N_SV 4000
#define N_SF 5000
#define NSAMP 50
#define N_SAMPLES 250000
// vertex grid (reverse term) — also used to sort samples; FIXED domain
#define GRID_G 32
#define NCELLS (GRID_G * GRID_G * GRID_G)       // 32768
#define SCAN_BLOCKS 32
// barycenter grid (forward term); FIXED domain
#define GRID_G2 32
#define NCELLS2 (GRID_G2 * GRID_G2 * GRID_G2)   // 32768
#define SCAN_BLOCKS2 32
#define REV_BLOCKS 977                           // ceil(250000/256)
#define FWD_WARP_BLOCKS 625                      // 5000 warps
#define FUSED_BLOCKS (FWD_WARP_BLOCKS + REV_BLOCKS)
#define GEN_BLOCKS 977
#define TOTAL_SCAN_BLOCKS 96

// fixed grid geometry (clamping is a convex projection => shell bound exact)
#define V_X0   (-5.0f)
#define V_H    (0.3125f)        // 10 / 32
#define V_INVH (3.2f)
#define B_X0   (-3.2f)
#define B_H    (0.2f)           // 6.4 / 32
#define B_INVH (5.0f)

// ---------------- device scratch (static, no runtime alloc) ----------------
__device__ float4    g_obp[N_OF];
__device__ float4    g_sb[N_SF];
__device__ unsigned  g_minfwd[N_SF];
__device__ float4    g_samples[N_SAMPLES];
__device__ float4    g_ssorted[N_SAMPLES];
__device__ float     g_sfp[N_SAMPLES];
__device__ unsigned  g_maxbits;          // reset by fused_nn tail
__device__ double    g_part[REV_BLOCKS];
__device__ unsigned  g_done;             // reset by fused_nn tail
__device__ int       g_scan_arrive;      // reset by scatter
// (cell, rank) recorded during the count pass -> atomic-free scatter
__device__ int       g_vcell[N_OV];
__device__ int       g_vrank[N_OV];
__device__ int       g_bcell[N_OF];
__device__ int       g_brank[N_OF];
__device__ int       g_scell[N_SAMPLES];
__device__ int       g_srank[N_SAMPLES];
// grid V (vertices)
__device__ int       g_count[NCELLS];    // zeroed by scatter (post-scan)
__device__ int       g_cellstart[NCELLS + 1];
__device__ int       g_blocksum[SCAN_BLOCKS];
__device__ float4    g_sorted[N_OV];
// grid B (original barycenters)
__device__ int       g_count2[NCELLS2];  // zeroed by scatter
__device__ int       g_cellstart2[NCELLS2 + 1];
__device__ int       g_blocksum2[SCAN_BLOCKS2];
__device__ float4    g_sorted2[N_OF];
// grid S (samples, same geometry as grid V)
__device__ int       g_count3[NCELLS];   // zeroed by scatter
__device__ int       g_cellstart3[NCELLS + 1];
__device__ int       g_blocksum3[SCAN_BLOCKS];

// ---------------- threefry2x32 (JAX partitionable, 20 rounds) ----------------
__host__ __device__ constexpr uint32_t rotl32(uint32_t x, int r) {
    return (x << r) | (x >> (32 - r));
}
struct U2 { uint32_t a, b; };
__host__ __device__ constexpr U2 threefry2x32(uint32_t k0, uint32_t k1,
                                              uint32_t x0, uint32_t x1) {
    uint32_t ks0 = k0, ks1 = k1, ks2 = k0 ^ k1 ^ 0x1BD11BDAu;
    x0 += ks0; x1 += ks1;
    x0 += x1; x1 = rotl32(x1, 13); x1 ^= x0;
    x0 += x1; x1 = rotl32(x1, 15); x1 ^= x0;
    x0 += x1; x1 = rotl32(x1, 26); x1 ^= x0;
    x0 += x1; x1 = rotl32(x1,  6); x1 ^= x0;
    x0 += ks1; x1 += ks2 + 1u;
    x0 += x1; x1 = rotl32(x1, 17); x1 ^= x0;
    x0 += x1; x1 = rotl32(x1, 29); x1 ^= x0;
    x0 += x1; x1 = rotl32(x1, 16); x1 ^= x0;
    x0 += x1; x1 = rotl32(x1, 24); x1 ^= x0;
    x0 += ks2; x1 += ks0 + 2u;
    x0 += x1; x1 = rotl32(x1, 13); x1 ^= x0;
    x0 += x1; x1 = rotl32(x1, 15); x1 ^= x0;
    x0 += x1; x1 = rotl32(x1, 26); x1 ^= x0;
    x0 += x1; x1 = rotl32(x1,  6); x1 ^= x0;
    x0 += ks0; x1 += ks1 + 3u;
    x0 += x1; x1 = rotl32(x1, 17); x1 ^= x0;
    x0 += x1; x1 = rotl32(x1, 29); x1 ^= x0;
    x0 += x1; x1 = rotl32(x1, 16); x1 ^= x0;
    x0 += x1; x1 = rotl32(x1, 24); x1 ^= x0;
    x0 += ks1; x1 += ks2 + 4u;
    x0 += x1; x1 = rotl32(x1, 13); x1 ^= x0;
    x0 += x1; x1 = rotl32(x1, 15); x1 ^= x0;
    x0 += x1; x1 = rotl32(x1, 26); x1 ^= x0;
    x0 += x1; x1 = rotl32(x1,  6); x1 ^= x0;
    x0 += ks2; x1 += ks0 + 5u;
    return {x0, x1};
}
constexpr U2 RK1 = threefry2x32(0u, 42u, 0u, 0u);
constexpr U2 RK2 = threefry2x32(0u, 42u, 0u, 1u);

__device__ __forceinline__ float bits_to_uniform(uint32_t bits) {
    return __uint_as_float((bits >> 9) | 0x3f800000u) - 1.0f;
}

// ---------------- fixed grid helpers ----------------
__device__ __forceinline__ int cc_v(float v) {
    int c = (int)((v - V_X0) * V_INVH);
    return min(max(c, 0), GRID_G - 1);
}
__device__ __forceinline__ int cc_b(float v) {
    int c = (int)((v - B_X0) * B_INVH);
    return min(max(c, 0), GRID_G2 - 1);
}

// ---------------- exact 1-NN: unrolled 3^3 box (MLP) + shells R>=2 ---------
// Fixed vertex grid. Clamping is a convex projection (1-Lipschitz), so the
// shell lower bound (R-1)*h holds for true distances — search is exact.
__device__ __forceinline__ float shell_nn_v(float qx, float qy, float qz, float qw,
                                            const int* __restrict__ cellstart,
                                            const float4* __restrict__ sorted) {
    const int G = GRID_G;
    float m2x = -2.0f * qx, m2y = -2.0f * qy, m2z = -2.0f * qz;
    int cx = cc_v(qx), cy = cc_v(qy), cz = cc_v(qz);

    int xlo = max(cx - 1, 0), xhi = min(cx + 1, G - 1);
    int ys[3], zs[3];
    ys[0] = max(cy - 1, 0); ys[1] = cy; ys[2] = min(cy + 1, G - 1);
    zs[0] = max(cz - 1, 0); zs[1] = cz; zs[2] = min(cz + 1, G - 1);
    int p0[9], p1[9];
#pragma unroll
    for (int a = 0; a < 3; a++) {
#pragma unroll
        for (int q = 0; q < 3; q++) {
            int rowbase = (zs[a] * G + ys[q]) * G;
            p0[a * 3 + q] = __ldg(&cellstart[rowbase + xlo]);
            p1[a * 3 + q] = __ldg(&cellstart[rowbase + xhi + 1]);
        }
    }
    float best = 3.0e38f;
#pragma unroll
    for (int r = 0; r < 9; r++) {
        for (int p = p0[r]; p < p1[r]; p++) {
            float4 v = sorted[p];
            float t = fmaf(v.x, m2x, fmaf(v.y, m2y, fmaf(v.z, m2z, v.w)));
            best = fminf(best, t);
        }
    }

    for (int R = 2; R <= G; R++) {
        float lb = (float)(R - 1) * V_H;
        if (best + qw <= lb * lb) break;
        int szlo = max(cz - R, 0), szhi = min(cz + R, G - 1);
        int sylo = max(cy - R, 0), syhi = min(cy + R, G - 1);
        int sxlo = max(cx - R, 0), sxhi = min(cx + R, G - 1);
        for (int z = szlo; z <= szhi; z++) {
            bool ze = (z == cz - R) || (z == cz + R);
            for (int y = sylo; y <= syhi; y++) {
                bool edge = ze || (y == cy - R) || (y == cy + R);
                int rowbase = (z * G + y) * G;
                if (edge) {
                    int q0 = __ldg(&cellstart[rowbase + sxlo]);
                    int q1 = __ldg(&cellstart[rowbase + sxhi + 1]);
                    for (int p = q0; p < q1; p++) {
                        float4 v = sorted[p];
                        float t = fmaf(v.x, m2x, fmaf(v.y, m2y, fmaf(v.z, m2z, v.w)));
                        best = fminf(best, t);
                    }
                } else {
                    int xa = cx - R, xb = cx + R;
                    if (xa >= 0) {
                        int c0 = rowbase + xa;
                        int q0 = __ldg(&cellstart[c0]), q1 = __ldg(&cellstart[c0 + 1]);
                        for (int p = q0; p < q1; p++) {
                            float4 v = sorted[p];
                            float t = fmaf(v.x, m2x, fmaf(v.y, m2y, fmaf(v.z, m2z, v.w)));
                            best = fminf(best, t);
                        }
                    }
                    if (xb <= G - 1) {
                        int c0 = rowbase + xb;
                        int q0 = __ldg(&cellstart[c0]), q1 = __ldg(&cellstart[c0 + 1]);
                        for (int p = q0; p < q1; p++) {
                            float4 v = sorted[p];
                            float t = fmaf(v.x, m2x, fmaf(v.y, m2y, fmaf(v.z, m2z, v.w)));
                            best = fminf(best, t);
                        }
                    }
                }
            }
        }
        if (szlo == 0 && sylo == 0 && sxlo == 0 &&
            szhi == G - 1 && syhi == G - 1 && sxhi == G - 1) break;
    }
    return fmaxf(best + qw, 0.0f);
}

// ---------------- kernel A: gen samples + barycenters + ALL counts ---------
__global__ void gen_count_kernel(const float* __restrict__ ov,
                                 const float* __restrict__ sv,
                                 const int*   __restrict__ sf,
                                 const int*   __restrict__ of) {
    int j = blockIdx.x * 256 + threadIdx.x;

    if (j < N_SAMPLES) {
        U2 ua = threefry2x32(RK1.a, RK1.b, 0u, (uint32_t)j);
        U2 ub = threefry2x32(RK2.a, RK2.b, 0u, (uint32_t)j);

        float u1 = bits_to_uniform(ua.a ^ ua.b);
        float r2 = bits_to_uniform(ub.a ^ ub.b);
        float sq = sqrtf(u1);
        float a = 1.0f - sq;
        float b = sq * (1.0f - r2);
        float c = sq * r2;
        int f = j / NSAMP;
        int i0 = sf[3 * f], i1 = sf[3 * f + 1], i2 = sf[3 * f + 2];
        float x = a * sv[3 * i0]     + b * sv[3 * i1]     + c * sv[3 * i2];
        float y = a * sv[3 * i0 + 1] + b * sv[3 * i1 + 1] + c * sv[3 * i2 + 1];
        float z = a * sv[3 * i0 + 2] + b * sv[3 * i1 + 2] + c * sv[3 * i2 + 2];
        g_samples[j] = make_float4(x, y, z, x * x + y * y + z * z);

        int c3 = (cc_v(z) * GRID_G + cc_v(y)) * GRID_G + cc_v(x);
        int rank = atomicAdd(&g_count3[c3], 1);
        g_scell[j] = c3;
        g_srank[j] = rank;
    }
    if (j < N_OV) {
        int c = (cc_v(ov[3 * j + 2]) * GRID_G + cc_v(ov[3 * j + 1])) * GRID_G
                + cc_v(ov[3 * j]);
        int rank = atomicAdd(&g_count[c], 1);
        g_vcell[j] = c;
        g_vrank[j] = rank;
    }
    if (j < N_OF) {
        int f0 = of[3 * j], f1 = of[3 * j + 1], f2 = of[3 * j + 2];
        float bx = (ov[3 * f0] + ov[3 * f1] + ov[3 * f2]) / 3.0f;
        float by = (ov[3 * f0 + 1] + ov[3 * f1 + 1] + ov[3 * f2 + 1]) / 3.0f;
        float bz = (ov[3 * f0 + 2] + ov[3 * f1 + 2] + ov[3 * f2 + 2]) / 3.0f;
        g_obp[j] = make_float4(bx, by, bz, bx * bx + by * by + bz * bz);
        int c = (cc_b(bz) * GRID_G2 + cc_b(by)) * GRID_G2 + cc_b(bx);
        int rank = atomicAdd(&g_count2[c], 1);
        g_bcell[j] = c;
        g_brank[j] = rank;
    }
    if (j < N_SF) {
        int f0 = sf[3 * j], f1 = sf[3 * j + 1], f2 = sf[3 * j + 2];
        float bx = (sv[3 * f0] + sv[3 * f1] + sv[3 * f2]) / 3.0f;
        float by = (sv[3 * f0 + 1] + sv[3 * f1 + 1] + sv[3 * f2 + 1]) / 3.0f;
        float bz = (sv[3 * f0 + 2] + sv[3 * f1 + 2] + sv[3 * f2 + 2]) / 3.0f;
        g_sb[j] = make_float4(bx, by, bz, bx * bx + by * by + bz * bz);
    }
}

// ---------------- kernel B: single-launch full scan (3 grids) --------------
__global__ void __launch_bounds__(1024) scan_kernel() {
    int b = blockIdx.x;
    int tid = threadIdx.x;
    const int* cnt;
    int* cs;
    int* bsum;
    int bb;
    int total_idx;
    if (b < SCAN_BLOCKS)                     { cnt = g_count;  cs = g_cellstart;  bsum = g_blocksum;  bb = b;               total_idx = NCELLS; }
    else if (b < SCAN_BLOCKS + SCAN_BLOCKS2) { cnt = g_count2; cs = g_cellstart2; bsum = g_blocksum2; bb = b - SCAN_BLOCKS; total_idx = NCELLS2; }
    else                                     { cnt = g_count3; cs = g_cellstart3; bsum = g_blocksum3; bb = b - SCAN_BLOCKS - SCAN_BLOCKS2; total_idx = NCELLS; }

    __shared__ int sd[1024];
    int cell = bb * 1024 + tid;
    int cv = cnt[cell];
    sd[tid] = cv;
    __syncthreads();
#pragma unroll
    for (int off = 1; off < 1024; off <<= 1) {
        int v = (tid >= off) ? sd[tid - off] : 0;
        __syncthreads();
        sd[tid] += v;
        __syncthreads();
    }
    int local_ex = sd[tid] - cv;

    if (tid == 1023) {
        bsum[bb] = sd[1023];
        __threadfence();
        atomicAdd(&g_scan_arrive, 1);
        while (atomicAdd(&g_scan_arrive, 0) < TOTAL_SCAN_BLOCKS) { }
    }
    __syncthreads();

    __shared__ int s_off, s_tot;
    if (tid < 32) {
        int v = bsum[tid];
        int s = v;
#pragma unroll
        for (int off = 1; off < 32; off <<= 1) {
            int t = __shfl_up_sync(0xffffffffu, s, off);
            if (tid >= off) s += t;
        }
        if (tid == bb) s_off = s - v;
        if (tid == 31) s_tot = s;
    }
    __syncthreads();
    cs[cell] = local_ex + s_off;
    if (bb == SCAN_BLOCKS - 1 && tid == 0) cs[total_idx] = s_tot;
}

// ---------------- kernel C: atomic-free scatter + state cleanup ------------
__global__ void scatter_kernel(const float* __restrict__ ov,
                               const float* __restrict__ fp) {
    int i = blockIdx.x * 256 + threadIdx.x;
    if (i < N_OV) {
        float x = ov[3 * i], y = ov[3 * i + 1], z = ov[3 * i + 2];
        int pos = __ldg(&g_cellstart[g_vcell[i]]) + g_vrank[i];
        g_sorted[pos] = make_float4(x, y, z, x * x + y * y + z * z);
    }
    if (i < N_OF) {
        int pos = __ldg(&g_cellstart2[g_bcell[i]]) + g_brank[i];
        g_sorted2[pos] = g_obp[i];
    }
    if (i < N_SAMPLES) {
        int pos = __ldg(&g_cellstart3[g_scell[i]]) + g_srank[i];
        g_ssorted[pos] = g_samples[i];
        g_sfp[pos] = fp[i / NSAMP];
    }
    // cleanup for next graph replay (counts are dead after scan)
    if (i < NCELLS)  { g_count[i] = 0; g_count3[i] = 0; }
    if (i < NCELLS2) { g_count2[i] = 0; }
    if (i == 0) g_scan_arrive = 0;
}

// ---------------- kernel D: fused forward + reverse + final ----------------
__global__ void __launch_bounds__(256) fused_nn_kernel(const float* __restrict__ fp,
                                                       float* __restrict__ out) {
    int b = blockIdx.x;
    int tid = threadIdx.x;

    if (b < FWD_WARP_BLOCKS) {
        // -------- forward: one warp per simplified barycenter --------
        int warp = (b * 256 + tid) >> 5;
        int lane = tid & 31;
        if (warp < N_SF) {
            float4 Q = g_sb[warp];
            float m2x = -2.0f * Q.x, m2y = -2.0f * Q.y, m2z = -2.0f * Q.z;
            int cx = cc_b(Q.x), cy = cc_b(Q.y), cz = cc_b(Q.z);
            const int G = GRID_G2;

            float best = 3.0e38f;
            for (int R = 0; R <= G; R++) {
                float bmin = best;
#pragma unroll
                for (int o = 16; o > 0; o >>= 1)
                    bmin = fminf(bmin, __shfl_xor_sync(0xffffffffu, bmin, o));
                if (R > 0) {
                    float lb = (float)(R - 1) * B_H;
                    if (bmin + Q.w <= lb * lb) break;
                }
                int zlo = max(cz - R, 0), zhi = min(cz + R, G - 1);
                int ylo = max(cy - R, 0), yhi = min(cy + R, G - 1);
                int xlo = max(cx - R, 0), xhi = min(cx + R, G - 1);
                for (int z = zlo; z <= zhi; z++) {
                    bool ze = (z == cz - R) || (z == cz + R);
                    for (int y = ylo; y <= yhi; y++) {
                        bool edge = ze || (y == cy - R) || (y == cy + R);
                        int rowbase = (z * G + y) * G;
                        if (edge) {
                            int p0 = __ldg(&g_cellstart2[rowbase + xlo]);
                            int p1 = __ldg(&g_cellstart2[rowbase + xhi + 1]);
                            for (int p = p0 + lane; p < p1; p += 32) {
                                float4 v = g_sorted2[p];
                                float t = fmaf(v.x, m2x, fmaf(v.y, m2y, fmaf(v.z, m2z, v.w)));
                                best = fminf(best, t);
                            }
                        } else {
                            int xa = cx - R, xb = cx + R;
                            if (xa >= 0) {
                                int c0 = rowbase + xa;
                                int p0 = __ldg(&g_cellstart2[c0]), p1 = __ldg(&g_cellstart2[c0 + 1]);
                                for (int p = p0 + lane; p < p1; p += 32) {
                                    float4 v = g_sorted2[p];
                                    float t = fmaf(v.x, m2x, fmaf(v.y, m2y, fmaf(v.z, m2z, v.w)));
                                    best = fminf(best, t);
                                }
                            }
                            if (xb <= G - 1) {
                                int c0 = rowbase + xb;
                                int p0 = __ldg(&g_cellstart2[c0]), p1 = __ldg(&g_cellstart2[c0 + 1]);
                                for (int p = p0 + lane; p < p1; p += 32) {
                                    float4 v = g_sorted2[p];
                                    float t = fmaf(v.x, m2x, fmaf(v.y, m2y, fmaf(v.z, m2z, v.w)));
                                    best = fminf(best, t);
                                }
                            }
                        }
                    }
                }
                if (zlo == 0 && ylo == 0 && xlo == 0 &&
                    zhi == G - 1 && yhi == G - 1 && xhi == G - 1) break;
            }
            float bmin = best;
#pragma unroll
            for (int o = 16; o > 0; o >>= 1)
                bmin = fminf(bmin, __shfl_xor_sync(0xffffffffu, bmin, o));
            if (lane == 0)
                g_minfwd[warp] = __float_as_uint(fmaxf(bmin + Q.w, 0.0f));
        }
    } else {
        // -------- reverse: one thread per cell-sorted sample --------
        int rb = b - FWD_WARP_BLOCKS;
        int j = rb * 256 + tid;

        float d = 0.0f;
        double contrib = 0.0;
        if (j < N_SAMPLES) {
            float4 s = g_ssorted[j];
            float d2 = shell_nn_v(s.x, s.y, s.z, s.w, g_cellstart, g_sorted);
            d = sqrtf(d2);
            contrib = (double)(g_sfp[j] * d);
        }

        __shared__ double rsum[256];
        __shared__ float rmax[256];
        rsum[tid] = contrib;
        rmax[tid] = d;
        __syncthreads();
#pragma unroll
        for (int o = 128; o > 0; o >>= 1) {
            if (tid < o) {
                rsum[tid] += rsum[tid + o];
                rmax[tid] = fmaxf(rmax[tid], rmax[tid + o]);
            }
            __syncthreads();
        }
        if (tid == 0) {
            g_part[rb] = rsum[0];
            atomicMax(&g_maxbits, __float_as_uint(rmax[0]));
        }
    }

    // -------- completion: last block runs the final reduction --------
    __syncthreads();
    __threadfence();
    __shared__ unsigned s_rank;
    if (tid == 0) s_rank = atomicAdd(&g_done, 1u);
    __syncthreads();
    if (s_rank != FUSED_BLOCKS - 1) return;

    __shared__ double red[256];
    double fwd = 0.0, pen = 0.0, rev = 0.0;
    for (int i = tid; i < N_SF; i += 256) {
        float p = fp[i];
        float d2 = __uint_as_float(g_minfwd[i]);
        fwd += (double)(p * sqrtf(d2));
        pen += (double)(1.0f - p);
    }
    for (int k = tid; k < REV_BLOCKS; k += 256) rev += g_part[k];

    double totF, totP, totR;
    red[tid] = fwd; __syncthreads();
#pragma unroll
    for (int o = 128; o > 0; o >>= 1) { if (tid < o) red[tid] += red[tid + o]; __syncthreads(); }
    totF = red[0]; __syncthreads();
    red[tid] = pen; __syncthreads();
#pragma unroll
    for (int o = 128; o > 0; o >>= 1) { if (tid < o) red[tid] += red[tid + o]; __syncthreads(); }
    totP = red[0]; __syncthreads();
    red[tid] = rev; __syncthreads();
#pragma unroll
    for (int o = 128; o > 0; o >>= 1) { if (tid < o) red[tid] += red[tid + o]; __syncthreads(); }
    totR = red[0];

    if (tid == 0) {
        double maxd = (double)__uint_as_float(g_maxbits);
        double result = totF + 1e-4 * totP + totR / (maxd + 1e-8) * 0.1;
        out[0] = (float)result;
        // cleanup for next graph replay (all blocks have arrived)
        g_done = 0u;
        g_maxbits = 0u;
    }
}

// ---------------- launch ----------------
extern "C" void kernel_launch(void* const* d_in, const int* in_sizes, int n_in,
                              void* d_out, int out_size) {
    const float* ov = (const float*)d_in[0];
    const int*   of = (const int*)  d_in[1];
    const float* sv = (const float*)d_in[2];
    const int*   sf = (const int*)  d_in[3];
    const float* fp = (const float*)d_in[4];
    float* out = (float*)d_out;

    gen_count_kernel<<<GEN_BLOCKS, 256>>>(ov, sv, sf, of);
    scan_kernel<<<TOTAL_SCAN_BLOCKS, 1024>>>();
    scatter_kernel<<<GEN_BLOCKS, 256>>>(ov, fp);
    fused_nn_kernel<<<FUSED_BLOCKS, 256>>>(fp, out);
}

// round 17
// speedup vs baseline: 1.4522x; 1.1400x over previous
#include <cuda_runtime.h>
#include <cuda_bf16.h>
#include <stdint.h>

// ---------------- problem constants (static shapes) ----------------
#define N_OV 20000
#define N_OF 30000
#define N_SV 4000
#define N_SF 5000
#define NSAMP 50
#define N_SAMPLES 250000
// vertex grid (reverse term) — also used to sort samples; FIXED domain
#define GRID_G 32
#define NCELLS (GRID_G * GRID_G * GRID_G)       // 32768
#define SCAN_BLOCKS 32
// barycenter grid (forward term); FIXED domain
#define GRID_G2 32
#define NCELLS2 (GRID_G2 * GRID_G2 * GRID_G2)   // 32768
#define SCAN_BLOCKS2 32
#define REV_BLOCKS 977                           // ceil(250000/256)
#define FWD_WARP_BLOCKS 625                      // 5000 warps
#define FUSED_BLOCKS (FWD_WARP_BLOCKS + REV_BLOCKS)
#define GEN_BLOCKS 977
#define TOTAL_SCAN_BLOCKS 96
#define NBUF 128                                 // staging buffer (float4 per warp)
#define UNION_VOL_CAP 96

// fixed grid geometry (clamping is a convex projection => shell bound exact)
#define V_X0   (-5.0f)
#define V_H    (0.3125f)
#define V_INVH (3.2f)
#define B_X0   (-3.2f)
#define B_H    (0.2f)
#define B_INVH (5.0f)

// ---------------- device scratch (static, no runtime alloc) ----------------
__device__ float4    g_obp[N_OF];
__device__ float4    g_sb[N_SF];
__device__ unsigned  g_minfwd[N_SF];
__device__ float4    g_samples[N_SAMPLES];
__device__ float4    g_ssorted[N_SAMPLES];
__device__ float     g_sfp[N_SAMPLES];
__device__ unsigned  g_maxbits;          // reset by fused_nn tail
__device__ double    g_part[REV_BLOCKS];
__device__ unsigned  g_done;             // reset by fused_nn tail
__device__ int       g_scan_arrive;      // reset by scatter
// (cell, rank) from count pass -> atomic-free scatter
__device__ int       g_vcell[N_OV];
__device__ int       g_vrank[N_OV];
__device__ int       g_bcell[N_OF];
__device__ int       g_brank[N_OF];
__device__ int       g_scell[N_SAMPLES];
__device__ int       g_srank[N_SAMPLES];
// grid V (vertices)
__device__ int       g_count[NCELLS];
__device__ int       g_cellstart[NCELLS + 1];
__device__ int       g_blocksum[SCAN_BLOCKS];
__device__ float4    g_sorted[N_OV];
// grid B (original barycenters)
__device__ int       g_count2[NCELLS2];
__device__ int       g_cellstart2[NCELLS2 + 1];
__device__ int       g_blocksum2[SCAN_BLOCKS2];
__device__ float4    g_sorted2[N_OF];
// grid S (samples)
__device__ int       g_count3[NCELLS];
__device__ int       g_cellstart3[NCELLS + 1];
__device__ int       g_blocksum3[SCAN_BLOCKS];

// ---------------- threefry2x32 (JAX partitionable, 20 rounds) ----------------
__host__ __device__ constexpr uint32_t rotl32(uint32_t x, int r) {
    return (x << r) | (x >> (32 - r));
}
struct U2 { uint32_t a, b; };
__host__ __device__ constexpr U2 threefry2x32(uint32_t k0, uint32_t k1,
                                              uint32_t x0, uint32_t x1) {
    uint32_t ks0 = k0, ks1 = k1, ks2 = k0 ^ k1 ^ 0x1BD11BDAu;
    x0 += ks0; x1 += ks1;
    x0 += x1; x1 = rotl32(x1, 13); x1 ^= x0;
    x0 += x1; x1 = rotl32(x1, 15); x1 ^= x0;
    x0 += x1; x1 = rotl32(x1, 26); x1 ^= x0;
    x0 += x1; x1 = rotl32(x1,  6); x1 ^= x0;
    x0 += ks1; x1 += ks2 + 1u;
    x0 += x1; x1 = rotl32(x1, 17); x1 ^= x0;
    x0 += x1; x1 = rotl32(x1, 29); x1 ^= x0;
    x0 += x1; x1 = rotl32(x1, 16); x1 ^= x0;
    x0 += x1; x1 = rotl32(x1, 24); x1 ^= x0;
    x0 += ks2; x1 += ks0 + 2u;
    x0 += x1; x1 = rotl32(x1, 13); x1 ^= x0;
    x0 += x1; x1 = rotl32(x1, 15); x1 ^= x0;
    x0 += x1; x1 = rotl32(x1, 26); x1 ^= x0;
    x0 += x1; x1 = rotl32(x1,  6); x1 ^= x0;
    x0 += ks0; x1 += ks1 + 3u;
    x0 += x1; x1 = rotl32(x1, 17); x1 ^= x0;
    x0 += x1; x1 = rotl32(x1, 29); x1 ^= x0;
    x0 += x1; x1 = rotl32(x1, 16); x1 ^= x0;
    x0 += x1; x1 = rotl32(x1, 24); x1 ^= x0;
    x0 += ks1; x1 += ks2 + 4u;
    x0 += x1; x1 = rotl32(x1, 13); x1 ^= x0;
    x0 += x1; x1 = rotl32(x1, 15); x1 ^= x0;
    x0 += x1; x1 = rotl32(x1, 26); x1 ^= x0;
    x0 += x1; x1 = rotl32(x1,  6); x1 ^= x0;
    x0 += ks2; x1 += ks0 + 5u;
    return {x0, x1};
}
constexpr U2 RK1 = threefry2x32(0u, 42u, 0u, 0u);
constexpr U2 RK2 = threefry2x32(0u, 42u, 0u, 1u);

__device__ __forceinline__ float bits_to_uniform(uint32_t bits) {
    return __uint_as_float((bits >> 9) | 0x3f800000u) - 1.0f;
}

// ---------------- fixed grid helpers ----------------
__device__ __forceinline__ int cc_v(float v) {
    int c = (int)((v - V_X0) * V_INVH);
    return min(max(c, 0), GRID_G - 1);
}
__device__ __forceinline__ int cc_b(float v) {
    int c = (int)((v - B_X0) * B_INVH);
    return min(max(c, 0), GRID_G2 - 1);
}

// ---------------- per-lane shell tail (R >= 2), given current best ---------
__device__ __forceinline__ float shell_tail_v(float qw, float m2x, float m2y, float m2z,
                                              int cx, int cy, int cz, float best,
                                              const int* __restrict__ cellstart,
                                              const float4* __restrict__ sorted) {
    const int G = GRID_G;
    for (int R = 2; R <= G; R++) {
        float lb = (float)(R - 1) * V_H;
        if (best + qw <= lb * lb) break;
        int szlo = max(cz - R, 0), szhi = min(cz + R, G - 1);
        int sylo = max(cy - R, 0), syhi = min(cy + R, G - 1);
        int sxlo = max(cx - R, 0), sxhi = min(cx + R, G - 1);
        for (int z = szlo; z <= szhi; z++) {
            bool ze = (z == cz - R) || (z == cz + R);
            for (int y = sylo; y <= syhi; y++) {
                bool edge = ze || (y == cy - R) || (y == cy + R);
                int rowbase = (z * G + y) * G;
                if (edge) {
                    int q0 = __ldg(&cellstart[rowbase + sxlo]);
                    int q1 = __ldg(&cellstart[rowbase + sxhi + 1]);
                    for (int p = q0; p < q1; p++) {
                        float4 v = sorted[p];
                        float t = fmaf(v.x, m2x, fmaf(v.y, m2y, fmaf(v.z, m2z, v.w)));
                        best = fminf(best, t);
                    }
                } else {
                    int xa = cx - R, xb = cx + R;
                    if (xa >= 0) {
                        int c0 = rowbase + xa;
                        int q0 = __ldg(&cellstart[c0]), q1 = __ldg(&cellstart[c0 + 1]);
                        for (int p = q0; p < q1; p++) {
                            float4 v = sorted[p];
                            float t = fmaf(v.x, m2x, fmaf(v.y, m2y, fmaf(v.z, m2z, v.w)));
                            best = fminf(best, t);
                        }
                    }
                    if (xb <= G - 1) {
                        int c0 = rowbase + xb;
                        int q0 = __ldg(&cellstart[c0]), q1 = __ldg(&cellstart[c0 + 1]);
                        for (int p = q0; p < q1; p++) {
                            float4 v = sorted[p];
                            float t = fmaf(v.x, m2x, fmaf(v.y, m2y, fmaf(v.z, m2z, v.w)));
                            best = fminf(best, t);
                        }
                    }
                }
            }
        }
        if (szlo == 0 && sylo == 0 && sxlo == 0 &&
            szhi == G - 1 && syhi == G - 1 && sxhi == G - 1) break;
    }
    return best;
}

// ---------------- per-lane 3^3 box (unrolled, MLP) ----------------
__device__ __forceinline__ float box_nn_v(float m2x, float m2y, float m2z,
                                          int cx, int cy, int cz,
                                          const int* __restrict__ cellstart,
                                          const float4* __restrict__ sorted) {
    const int G = GRID_G;
    int xlo = max(cx - 1, 0), xhi = min(cx + 1, G - 1);
    int ys[3], zs[3];
    ys[0] = max(cy - 1, 0); ys[1] = cy; ys[2] = min(cy + 1, G - 1);
    zs[0] = max(cz - 1, 0); zs[1] = cz; zs[2] = min(cz + 1, G - 1);
    int p0[9], p1[9];
#pragma unroll
    for (int a = 0; a < 3; a++)
#pragma unroll
        for (int q = 0; q < 3; q++) {
            int rowbase = (zs[a] * G + ys[q]) * G;
            p0[a * 3 + q] = __ldg(&cellstart[rowbase + xlo]);
            p1[a * 3 + q] = __ldg(&cellstart[rowbase + xhi + 1]);
        }
    float best = 3.0e38f;
#pragma unroll
    for (int r = 0; r < 9; r++)
        for (int p = p0[r]; p < p1[r]; p++) {
            float4 v = sorted[p];
            float t = fmaf(v.x, m2x, fmaf(v.y, m2y, fmaf(v.z, m2z, v.w)));
            best = fminf(best, t);
        }
    return best;
}

// ---------------- kernel A: gen samples + barycenters + ALL counts ---------
__global__ void gen_count_kernel(const float* __restrict__ ov,
                                 const float* __restrict__ sv,
                                 const int*   __restrict__ sf,
                                 const int*   __restrict__ of) {
    int j = blockIdx.x * 256 + threadIdx.x;

    if (j < N_SAMPLES) {
        U2 ua = threefry2x32(RK1.a, RK1.b, 0u, (uint32_t)j);
        U2 ub = threefry2x32(RK2.a, RK2.b, 0u, (uint32_t)j);

        float u1 = bits_to_uniform(ua.a ^ ua.b);
        float r2 = bits_to_uniform(ub.a ^ ub.b);
        float sq = sqrtf(u1);
        float a = 1.0f - sq;
        float b = sq * (1.0f - r2);
        float c = sq * r2;
        int f = j / NSAMP;
        int i0 = sf[3 * f], i1 = sf[3 * f + 1], i2 = sf[3 * f + 2];
        float x = a * sv[3 * i0]     + b * sv[3 * i1]     + c * sv[3 * i2];
        float y = a * sv[3 * i0 + 1] + b * sv[3 * i1 + 1] + c * sv[3 * i2 + 1];
        float z = a * sv[3 * i0 + 2] + b * sv[3 * i1 + 2] + c * sv[3 * i2 + 2];
        g_samples[j] = make_float4(x, y, z, x * x + y * y + z * z);

        int c3 = (cc_v(z) * GRID_G + cc_v(y)) * GRID_G + cc_v(x);
        int rank = atomicAdd(&g_count3[c3], 1);
        g_scell[j] = c3;
        g_srank[j] = rank;
    }
    if (j < N_OV) {
        int c = (cc_v(ov[3 * j + 2]) * GRID_G + cc_v(ov[3 * j + 1])) * GRID_G
                + cc_v(ov[3 * j]);
        int rank = atomicAdd(&g_count[c], 1);
        g_vcell[j] = c;
        g_vrank[j] = rank;
    }
    if (j < N_OF) {
        int f0 = of[3 * j], f1 = of[3 * j + 1], f2 = of[3 * j + 2];
        float bx = (ov[3 * f0] + ov[3 * f1] + ov[3 * f2]) / 3.0f;
        float by = (ov[3 * f0 + 1] + ov[3 * f1 + 1] + ov[3 * f2 + 1]) / 3.0f;
        float bz = (ov[3 * f0 + 2] + ov[3 * f1 + 2] + ov[3 * f2 + 2]) / 3.0f;
        g_obp[j] = make_float4(bx, by, bz, bx * bx + by * by + bz * bz);
        int c = (cc_b(bz) * GRID_G2 + cc_b(by)) * GRID_G2 + cc_b(bx);
        int rank = atomicAdd(&g_count2[c], 1);
        g_bcell[j] = c;
        g_brank[j] = rank;
    }
    if (j < N_SF) {
        int f0 = sf[3 * j], f1 = sf[3 * j + 1], f2 = sf[3 * j + 2];
        float bx = (sv[3 * f0] + sv[3 * f1] + sv[3 * f2]) / 3.0f;
        float by = (sv[3 * f0 + 1] + sv[3 * f1 + 1] + sv[3 * f2 + 1]) / 3.0f;
        float bz = (sv[3 * f0 + 2] + sv[3 * f1 + 2] + sv[3 * f2 + 2]) / 3.0f;
        g_sb[j] = make_float4(bx, by, bz, bx * bx + by * by + bz * bz);
    }
}

// ---------------- kernel B: single-launch full scan (3 grids) --------------
__global__ void __launch_bounds__(1024) scan_kernel() {
    int b = blockIdx.x;
    int tid = threadIdx.x;
    const int* cnt;
    int* cs;
    int* bsum;
    int bb;
    int total_idx;
    if (b < SCAN_BLOCKS)                     { cnt = g_count;  cs = g_cellstart;  bsum = g_blocksum;  bb = b;               total_idx = NCELLS; }
    else if (b < SCAN_BLOCKS + SCAN_BLOCKS2) { cnt = g_count2; cs = g_cellstart2; bsum = g_blocksum2; bb = b - SCAN_BLOCKS; total_idx = NCELLS2; }
    else                                     { cnt = g_count3; cs = g_cellstart3; bsum = g_blocksum3; bb = b - SCAN_BLOCKS - SCAN_BLOCKS2; total_idx = NCELLS; }

    __shared__ int sd[1024];
    int cell = bb * 1024 + tid;
    int cv = cnt[cell];
    sd[tid] = cv;
    __syncthreads();
#pragma unroll
    for (int off = 1; off < 1024; off <<= 1) {
        int v = (tid >= off) ? sd[tid - off] : 0;
        __syncthreads();
        sd[tid] += v;
        __syncthreads();
    }
    int local_ex = sd[tid] - cv;

    if (tid == 1023) {
        bsum[bb] = sd[1023];
        __threadfence();
        atomicAdd(&g_scan_arrive, 1);
        while (atomicAdd(&g_scan_arrive, 0) < TOTAL_SCAN_BLOCKS) { }
    }
    __syncthreads();

    __shared__ int s_off, s_tot;
    if (tid < 32) {
        int v = bsum[tid];
        int s = v;
#pragma unroll
        for (int off = 1; off < 32; off <<= 1) {
            int t = __shfl_up_sync(0xffffffffu, s, off);
            if (tid >= off) s += t;
        }
        if (tid == bb) s_off = s - v;
        if (tid == 31) s_tot = s;
    }
    __syncthreads();
    cs[cell] = local_ex + s_off;
    if (bb == SCAN_BLOCKS - 1 && tid == 0) cs[total_idx] = s_tot;
}

// ---------------- kernel C: atomic-free scatter + state cleanup ------------
__global__ void scatter_kernel(const float* __restrict__ ov,
                               const float* __restrict__ fp) {
    int i = blockIdx.x * 256 + threadIdx.x;
    if (i < N_OV) {
        float x = ov[3 * i], y = ov[3 * i + 1], z = ov[3 * i + 2];
        int pos = __ldg(&g_cellstart[g_vcell[i]]) + g_vrank[i];
        g_sorted[pos] = make_float4(x, y, z, x * x + y * y + z * z);
    }
    if (i < N_OF) {
        int pos = __ldg(&g_cellstart2[g_bcell[i]]) + g_brank[i];
        g_sorted2[pos] = g_obp[i];
    }
    if (i < N_SAMPLES) {
        int pos = __ldg(&g_cellstart3[g_scell[i]]) + g_srank[i];
        g_ssorted[pos] = g_samples[i];
        g_sfp[pos] = fp[i / NSAMP];
    }
    if (i < NCELLS)  { g_count[i] = 0; g_count3[i] = 0; }
    if (i < NCELLS2) { g_count2[i] = 0; }
    if (i == 0) g_scan_arrive = 0;
}

// ---------------- kernel D: fused forward + reverse + final ----------------
__global__ void __launch_bounds__(256) fused_nn_kernel(const float* __restrict__ fp,
                                                       float* __restrict__ out) {
    __shared__ float4 sbuf[8][NBUF];   // per-warp staging (reverse coop path)
    int b = blockIdx.x;
    int tid = threadIdx.x;

    if (b < FWD_WARP_BLOCKS) {
        // -------- forward: one warp per simplified barycenter --------
        int warp = (b * 256 + tid) >> 5;
        int lane = tid & 31;
        if (warp < N_SF) {
            float4 Q = g_sb[warp];
            float m2x = -2.0f * Q.x, m2y = -2.0f * Q.y, m2z = -2.0f * Q.z;
            int cx = cc_b(Q.x), cy = cc_b(Q.y), cz = cc_b(Q.z);
            const int G = GRID_G2;

            float best = 3.0e38f;
            for (int R = 0; R <= G; R++) {
                float bmin = best;
#pragma unroll
                for (int o = 16; o > 0; o >>= 1)
                    bmin = fminf(bmin, __shfl_xor_sync(0xffffffffu, bmin, o));
                if (R > 0) {
                    float lb = (float)(R - 1) * B_H;
                    if (bmin + Q.w <= lb * lb) break;
                }
                int zlo = max(cz - R, 0), zhi = min(cz + R, G - 1);
                int ylo = max(cy - R, 0), yhi = min(cy + R, G - 1);
                int xlo = max(cx - R, 0), xhi = min(cx + R, G - 1);
                for (int z = zlo; z <= zhi; z++) {
                    bool ze = (z == cz - R) || (z == cz + R);
                    for (int y = ylo; y <= yhi; y++) {
                        bool edge = ze || (y == cy - R) || (y == cy + R);
                        int rowbase = (z * G + y) * G;
                        if (edge) {
                            int p0 = __ldg(&g_cellstart2[rowbase + xlo]);
                            int p1 = __ldg(&g_cellstart2[rowbase + xhi + 1]);
                            for (int p = p0 + lane; p < p1; p += 32) {
                                float4 v = g_sorted2[p];
                                float t = fmaf(v.x, m2x, fmaf(v.y, m2y, fmaf(v.z, m2z, v.w)));
                                best = fminf(best, t);
                            }
                        } else {
                            int xa = cx - R, xb = cx + R;
                            if (xa >= 0) {
                                int c0 = rowbase + xa;
                                int p0 = __ldg(&g_cellstart2[c0]), p1 = __ldg(&g_cellstart2[c0 + 1]);
                                for (int p = p0 + lane; p < p1; p += 32) {
                                    float4 v = g_sorted2[p];
                                    float t = fmaf(v.x, m2x, fmaf(v.y, m2y, fmaf(v.z, m2z, v.w)));
                                    best = fminf(best, t);
                                }
                            }
                            if (xb <= G - 1) {
                                int c0 = rowbase + xb;
                                int p0 = __ldg(&g_cellstart2[c0]), p1 = __ldg(&g_cellstart2[c0 + 1]);
                                for (int p = p0 + lane; p < p1; p += 32) {
                                    float4 v = g_sorted2[p];
                                    float t = fmaf(v.x, m2x, fmaf(v.y, m2y, fmaf(v.z, m2z, v.w)));
                                    best = fminf(best, t);
                                }
                            }
                        }
                    }
                }
                if (zlo == 0 && ylo == 0 && xlo == 0 &&
                    zhi == G - 1 && yhi == G - 1 && xhi == G - 1) break;
            }
            float bmin = best;
#pragma unroll
            for (int o = 16; o > 0; o >>= 1)
                bmin = fminf(bmin, __shfl_xor_sync(0xffffffffu, bmin, o));
            if (lane == 0)
                g_minfwd[warp] = __float_as_uint(fmaxf(bmin + Q.w, 0.0f));
        }
    } else {
        // -------- reverse: warp-cooperative over 32 sorted samples --------
        const int G = GRID_G;
        int rb = b - FWD_WARP_BLOCKS;
        int wib = tid >> 5;
        int lane = tid & 31;
        int j = rb * 256 + tid;
        bool valid = (j < N_SAMPLES);
        int jl = valid ? j : N_SAMPLES - 1;

        float4 s = g_ssorted[jl];
        float m2x = -2.0f * s.x, m2y = -2.0f * s.y, m2z = -2.0f * s.z;
        int cx = cc_v(s.x), cy = cc_v(s.y), cz = cc_v(s.z);
        int xlo = max(cx - 1, 0), xhi = min(cx + 1, G - 1);
        int ylo = max(cy - 1, 0), yhi = min(cy + 1, G - 1);
        int zlo = max(cz - 1, 0), zhi = min(cz + 1, G - 1);

        // warp union of own boxes
        int uxlo = xlo, uxhi = xhi, uylo = ylo, uyhi = yhi, uzlo = zlo, uzhi = zhi;
#pragma unroll
        for (int o = 16; o > 0; o >>= 1) {
            uxlo = min(uxlo, __shfl_xor_sync(0xffffffffu, uxlo, o));
            uxhi = max(uxhi, __shfl_xor_sync(0xffffffffu, uxhi, o));
            uylo = min(uylo, __shfl_xor_sync(0xffffffffu, uylo, o));
            uyhi = max(uyhi, __shfl_xor_sync(0xffffffffu, uyhi, o));
            uzlo = min(uzlo, __shfl_xor_sync(0xffffffffu, uzlo, o));
            uzhi = max(uzhi, __shfl_xor_sync(0xffffffffu, uzhi, o));
        }
        int vol = (uxhi - uxlo + 1) * (uyhi - uylo + 1) * (uzhi - uzlo + 1);

        float best;
        if (vol <= UNION_VOL_CAP) {
            // cooperative staging of the union box (warp-uniform control flow)
            float4* buf = sbuf[wib];
            best = 3.0e38f;
            int cnt = 0;
            for (int z = uzlo; z <= uzhi; z++) {
                for (int y = uylo; y <= uyhi; y++) {
                    int rowbase = (z * G + y) * G;
                    int p0 = __ldg(&g_cellstart[rowbase + uxlo]);
                    int p1 = __ldg(&g_cellstart[rowbase + uxhi + 1]);
                    int len = p1 - p0;
                    int off = 0;
                    while (off < len) {
                        if (cnt == NBUF) {
                            __syncwarp();
                            for (int k = 0; k < cnt; k++) {
                                float4 v = buf[k];
                                float t = fmaf(v.x, m2x, fmaf(v.y, m2y, fmaf(v.z, m2z, v.w)));
                                best = fminf(best, t);
                            }
                            __syncwarp();
                            cnt = 0;
                        }
                        int take = min(len - off, NBUF - cnt);
                        for (int t = lane; t < take; t += 32)
                            buf[cnt + t] = g_sorted[p0 + off + t];
                        cnt += take;
                        off += take;
                    }
                }
            }
            __syncwarp();
            for (int k = 0; k < cnt; k++) {
                float4 v = buf[k];
                float t = fmaf(v.x, m2x, fmaf(v.y, m2y, fmaf(v.z, m2z, v.w)));
                best = fminf(best, t);
            }
            // certified: outside own 3^3 box => distance >= V_H
            if (best + s.w > V_H * V_H)
                best = shell_tail_v(s.w, m2x, m2y, m2z, cx, cy, cz, best,
                                    g_cellstart, g_sorted);
        } else {
            // sparse / boundary-crossing warp: per-lane path
            best = box_nn_v(m2x, m2y, m2z, cx, cy, cz, g_cellstart, g_sorted);
            if (best + s.w > V_H * V_H)
                best = shell_tail_v(s.w, m2x, m2y, m2z, cx, cy, cz, best,
                                    g_cellstart, g_sorted);
        }

        float d = 0.0f;
        double contrib = 0.0;
        if (valid) {
            d = sqrtf(fmaxf(best + s.w, 0.0f));
            contrib = (double)(g_sfp[j] * d);
        }

        __shared__ double rsum[256];
        __shared__ float rmax[256];
        rsum[tid] = contrib;
        rmax[tid] = d;
        __syncthreads();
#pragma unroll
        for (int o = 128; o > 0; o >>= 1) {
            if (tid < o) {
                rsum[tid] += rsum[tid + o];
                rmax[tid] = fmaxf(rmax[tid], rmax[tid + o]);
            }
            __syncthreads();
        }
        if (tid == 0) {
            g_part[rb] = rsum[0];
            atomicMax(&g_maxbits, __float_as_uint(rmax[0]));
        }
    }

    // -------- completion: last block runs the final reduction --------
    __syncthreads();
    __threadfence();
    __shared__ unsigned s_rank;
    if (tid == 0) s_rank = atomicAdd(&g_done, 1u);
    __syncthreads();
    if (s_rank != FUSED_BLOCKS - 1) return;

    __shared__ double red[256];
    double fwd = 0.0, pen = 0.0, rev = 0.0;
    for (int i = tid; i < N_SF; i += 256) {
        float p = fp[i];
        float d2 = __uint_as_float(g_minfwd[i]);
        fwd += (double)(p * sqrtf(d2));
        pen += (double)(1.0f - p);
    }
    for (int k = tid; k < REV_BLOCKS; k += 256) rev += g_part[k];

    double totF, totP, totR;
    red[tid] = fwd; __syncthreads();
#pragma unroll
    for (int o = 128; o > 0; o >>= 1) { if (tid < o) red[tid] += red[tid + o]; __syncthreads(); }
    totF = red[0]; __syncthreads();
    red[tid] = pen; __syncthreads();
#pragma unroll
    for (int o = 128; o > 0; o >>= 1) { if (tid < o) red[tid] += red[tid + o]; __syncthreads(); }
    totP = red[0]; __syncthreads();
    red[tid] = rev; __syncthreads();
#pragma unroll
    for (int o = 128; o > 0; o >>= 1) { if (tid < o) red[tid] += red[tid + o]; __syncthreads(); }
    totR = red[0];

    if (tid == 0) {
        double maxd = (double)__uint_as_float(g_maxbits);
        double result = totF + 1e-4 * totP + totR / (maxd + 1e-8) * 0.1;
        out[0] = (float)result;
        g_done = 0u;
        g_maxbits = 0u;
    }
}

// ---------------- launch ----------------
extern "C" void kernel_launch(void* const* d_in, const int* in_sizes, int n_in,
                              void* d_out, int out_size) {
    const float* ov = (const float*)d_in[0];
    const int*   of = (const int*)  d_in[1];
    const float* sv = (const float*)d_in[2];
    const int*   sf = (const int*)  d_in[3];
    const float* fp = (const float*)d_in[4];
    float* out = (float*)d_out;

    gen_count_kernel<<<GEN_BLOCKS, 256>>>(ov, sv, sf, of);
    scan_kernel<<<TOTAL_SCAN_BLOCKS, 1024>>>();
    scatter_kernel<<<GEN_BLOCKS, 256>>>(ov, fp);
    fused_nn_kernel<<<FUSED_BLOCKS, 256>>>(fp, out);
}